// round 1
// baseline (speedup 1.0000x reference)
#include <cuda_runtime.h>

#define NP 200000
#define KN 16
#define MR 3200000
#define H1C 16
#define H2C 32
#define CC 64
#define HD 256
#define BNEPS 1e-5

// ---------------- scratch (no allocations allowed) ----------------
__device__ double g_S1[H1C], g_Q1[H1C];
__device__ double g_S2[H2C], g_Q2[H2C];
__device__ double g_S3[CC],  g_Q3[CC];
__device__ float  g_par1[2*H1C];   // scale, shift for BN1 (folded with g1/b1)
__device__ float  g_par2[2*H2C];   // scale, shift for BN2
__device__ float  g_sc3[CC], g_sh3[CC];
__device__ float  g_pooled[NP*CC]; // 51.2 MB
__device__ float  g_Weff[CC*HD];
__device__ float  g_bias[HD];

typedef unsigned long long u64;

// ---------------- packed f32x2 helpers (Blackwell) ----------------
__device__ __forceinline__ u64 pk2(float lo, float hi){
    u64 r; asm("mov.b64 %0, {%1, %2};" : "=l"(r) : "f"(lo), "f"(hi)); return r;
}
__device__ __forceinline__ void up2(u64 v, float &lo, float &hi){
    asm("mov.b64 {%0, %1}, %2;" : "=f"(lo), "=f"(hi) : "l"(v));
}
__device__ __forceinline__ u64 f2fma(u64 a, u64 b, u64 c){
    u64 r; asm("fma.rn.f32x2 %0, %1, %2, %3;" : "=l"(r) : "l"(a), "l"(b), "l"(c)); return r;
}

__device__ __forceinline__ float gelu(float v){
    return 0.5f*v*(1.0f + erff(v*0.70710678118654752f));
}

__device__ __forceinline__ void gather7(const float* __restrict__ p, const float* __restrict__ f,
                                        int n, int idx, float x[7]){
    float px = p[3*n], py = p[3*n+1], pz = p[3*n+2];
    x[0] = p[3*idx]   - px;
    x[1] = p[3*idx+1] - py;
    x[2] = p[3*idx+2] - pz;
    float4 fv = *reinterpret_cast<const float4*>(f + 4*idx);
    x[3]=fv.x; x[4]=fv.y; x[5]=fv.z; x[6]=fv.w;
}

// a = x @ w1   (w1 shared, row-major [7][16])
__device__ __forceinline__ void lin1(const float x[7], const float* sw1, float a[H1C]){
    u64 acc[8];
    #pragma unroll
    for(int u=0;u<8;u++) acc[u]=0ull;
    #pragma unroll
    for(int i=0;i<7;i++){
        u64 xp = pk2(x[i], x[i]);
        const u64* w = reinterpret_cast<const u64*>(sw1 + i*H1C);
        #pragma unroll
        for(int u=0;u<8;u++) acc[u] = f2fma(xp, w[u], acc[u]);
    }
    #pragma unroll
    for(int u=0;u<8;u++) up2(acc[u], a[2*u], a[2*u+1]);
}

// a = h @ w2   (w2 shared, row-major [16][32])
__device__ __forceinline__ void lin2(const float h[H1C], const float* sw2, float a[H2C]){
    u64 acc[16];
    #pragma unroll
    for(int u=0;u<16;u++) acc[u]=0ull;
    #pragma unroll
    for(int i=0;i<H1C;i++){
        u64 hp = pk2(h[i], h[i]);
        const u64* w = reinterpret_cast<const u64*>(sw2 + i*H2C);
        #pragma unroll
        for(int u=0;u<16;u++) acc[u] = f2fma(hp, w[u], acc[u]);
    }
    #pragma unroll
    for(int u=0;u<16;u++) up2(acc[u], a[2*u], a[2*u+1]);
}

__device__ __forceinline__ float wred(float v){
    #pragma unroll
    for(int o=16;o>0;o>>=1) v += __shfl_down_sync(0xffffffffu, v, o);
    return v;
}

// ---------------- kernels ----------------
__global__ void k_init(){
    int t = threadIdx.x;
    if(t<H1C){ g_S1[t]=0.0; g_Q1[t]=0.0; }
    if(t<H2C){ g_S2[t]=0.0; g_Q2[t]=0.0; }
    if(t<CC){ g_S3[t]=0.0; g_Q3[t]=0.0; }
}

// stats of a1 = x @ w1 over all 3.2M rows
__global__ void k_pass1(const float* __restrict__ p, const float* __restrict__ f,
                        const int* __restrict__ gi, const float* __restrict__ w1){
    __shared__ __align__(16) float sw1[7*H1C];
    int t = threadIdx.x;
    if(t < 7*H1C) sw1[t] = w1[t];
    __syncthreads();
    float s[H1C], q[H1C];
    #pragma unroll
    for(int j=0;j<H1C;j++){ s[j]=0.f; q[j]=0.f; }
    int stride = gridDim.x * blockDim.x;
    for(int r = blockIdx.x*blockDim.x + t; r < MR; r += stride){
        int n = r >> 4;
        float x[7]; gather7(p, f, n, gi[r], x);
        float a[H1C]; lin1(x, sw1, a);
        #pragma unroll
        for(int j=0;j<H1C;j++){ s[j]+=a[j]; q[j]+=a[j]*a[j]; }
    }
    __shared__ float red[2*H1C];
    if(t < 2*H1C) red[t]=0.f;
    __syncthreads();
    int lane = t & 31;
    #pragma unroll
    for(int j=0;j<H1C;j++){
        float sv = wred(s[j]);
        float qv = wred(q[j]);
        if(lane==0){ atomicAdd(&red[j], sv); atomicAdd(&red[H1C+j], qv); }
    }
    __syncthreads();
    if(t < H1C) atomicAdd(&g_S1[t], (double)red[t]);
    else if(t < 2*H1C) atomicAdd(&g_Q1[t-H1C], (double)red[t]);
}

__global__ void k_stats1(const float* __restrict__ g1, const float* __restrict__ b1){
    int j = threadIdx.x;
    if(j >= H1C) return;
    double m = g_S1[j] / (double)MR;
    double v = g_Q1[j] / (double)MR - m*m;
    double rs = rsqrt(v + BNEPS);
    float sc = (float)((double)g1[j] * rs);
    g_par1[j] = sc;
    g_par1[H1C+j] = b1[j] - (float)m * sc;
}

// stats of a2 = gelu(bn1(a1)) @ w2
__global__ void k_pass2(const float* __restrict__ p, const float* __restrict__ f,
                        const int* __restrict__ gi, const float* __restrict__ w1,
                        const float* __restrict__ w2){
    __shared__ __align__(16) float sw1[7*H1C];
    __shared__ __align__(16) float sw2[H1C*H2C];
    __shared__ float sp1[2*H1C];
    int t=threadIdx.x;
    if(t<7*H1C) sw1[t]=w1[t];
    if(t<2*H1C) sp1[t]=g_par1[t];
    for(int i=t;i<H1C*H2C;i+=blockDim.x) sw2[i]=w2[i];
    __syncthreads();
    float s[H2C], q[H2C];
    #pragma unroll
    for(int j=0;j<H2C;j++){s[j]=0.f;q[j]=0.f;}
    int stride=gridDim.x*blockDim.x;
    for(int r=blockIdx.x*blockDim.x+t; r<MR; r+=stride){
        int n=r>>4;
        float x[7]; gather7(p,f,n,gi[r],x);
        float a1[H1C]; lin1(x,sw1,a1);
        float h1[H1C];
        #pragma unroll
        for(int j=0;j<H1C;j++) h1[j]=gelu(a1[j]*sp1[j]+sp1[H1C+j]);
        float a2[H2C]; lin2(h1,sw2,a2);
        #pragma unroll
        for(int j=0;j<H2C;j++){s[j]+=a2[j];q[j]+=a2[j]*a2[j];}
    }
    __shared__ float red[2*H2C];
    if(t<2*H2C) red[t]=0.f;
    __syncthreads();
    int lane=t&31;
    #pragma unroll
    for(int j=0;j<H2C;j++){
        float sv=wred(s[j]), qv=wred(q[j]);
        if(lane==0){atomicAdd(&red[j],sv);atomicAdd(&red[H2C+j],qv);}
    }
    __syncthreads();
    if(t<H2C) atomicAdd(&g_S2[t],(double)red[t]);
    else if(t<2*H2C) atomicAdd(&g_Q2[t-H2C],(double)red[t]);
}

__global__ void k_stats2(const float* __restrict__ g2, const float* __restrict__ b2){
    int j = threadIdx.x;
    if(j >= H2C) return;
    double m = g_S2[j] / (double)MR;
    double v = g_Q2[j] / (double)MR - m*m;
    double rs = rsqrt(v + BNEPS);
    float sc = (float)((double)g2[j] * rs);
    g_par2[j] = sc;
    g_par2[H2C+j] = b2[j] - (float)m * sc;
}

// full MLP -> a3 = h2 @ w3 -> max over K neighbors -> g_pooled
__global__ void __launch_bounds__(128) k_pass3(const float* __restrict__ p, const float* __restrict__ f,
    const int* __restrict__ gi, const float* __restrict__ w1, const float* __restrict__ w2,
    const float* __restrict__ w3){
    __shared__ __align__(16) float sw1[7*H1C];
    __shared__ __align__(16) float sw2[H1C*H2C];
    __shared__ __align__(16) float sw3[H2C*CC];
    __shared__ float sp1[2*H1C];
    __shared__ float sp2[2*H2C];
    __shared__ float h2s[128*33];   // odd stride: the two half-warps hit distinct banks
    int t = threadIdx.x;
    if(t < 7*H1C) sw1[t]=w1[t];
    if(t < 2*H1C) sp1[t]=g_par1[t];
    if(t < 2*H2C) sp2[t]=g_par2[t];
    for(int i=t;i<H1C*H2C;i+=128) sw2[i]=w2[i];
    for(int i=t;i<H2C*CC;i+=128) sw3[i]=w3[i];
    __syncthreads();

    // stage A: one thread per (point,neighbor) row -> h2 into shared
    int n = blockIdx.x*8 + (t>>4);
    int r = (n<<4) + (t&15);
    float x[7]; gather7(p,f,n,gi[r],x);
    float a1[H1C]; lin1(x, sw1, a1);
    float h1[H1C];
    #pragma unroll
    for(int j=0;j<H1C;j++) h1[j] = gelu(a1[j]*sp1[j] + sp1[H1C+j]);
    float a2[H2C]; lin2(h1, sw2, a2);
    float* hw = &h2s[t*33];
    #pragma unroll
    for(int j=0;j<H2C;j++) hw[j] = gelu(a2[j]*sp2[j] + sp2[H2C+j]);
    __syncthreads();

    // stage B: thread = (local point, 4 channels); h2 @ w3 with running max over k
    int pl = t>>4;
    int c0 = (t&15)*4;
    float m0=-3.4e38f, m1=-3.4e38f, m2=-3.4e38f, m3=-3.4e38f;
    #pragma unroll 1
    for(int k=0;k<KN;k++){
        const float* hr = &h2s[(pl*KN + k)*33];
        u64 a01=0ull, a23=0ull;
        #pragma unroll
        for(int kk=0;kk<H2C;kk++){
            u64 hp = pk2(hr[kk], hr[kk]);
            ulonglong2 w = *reinterpret_cast<const ulonglong2*>(sw3 + kk*CC + c0);
            a01 = f2fma(hp, w.x, a01);
            a23 = f2fma(hp, w.y, a23);
        }
        float v0,v1,v2,v3; up2(a01,v0,v1); up2(a23,v2,v3);
        m0=fmaxf(m0,v0); m1=fmaxf(m1,v1); m2=fmaxf(m2,v2); m3=fmaxf(m3,v3);
    }
    int np = blockIdx.x*8 + pl;
    float4 o; o.x=m0; o.y=m1; o.z=m2; o.w=m3;
    *reinterpret_cast<float4*>(g_pooled + np*CC + c0) = o;
}

// per-channel stats of pooled
__global__ void k_red3(){
    __shared__ float ss[CC], sq[CC];
    int t=threadIdx.x;
    if(t<CC){ss[t]=0.f;sq[t]=0.f;}
    __syncthreads();
    float s=0.f,q=0.f;
    int stride = gridDim.x*blockDim.x;   // multiple of 64 -> channel stays fixed
    int i0 = blockIdx.x*blockDim.x + t;
    for(int i=i0;i<NP*CC;i+=stride){ float v=g_pooled[i]; s+=v; q+=v*v; }
    int c = i0 & (CC-1);
    atomicAdd(&ss[c], s); atomicAdd(&sq[c], q);
    __syncthreads();
    if(t<CC) atomicAdd(&g_S3[t],(double)ss[t]);
    else if(t<2*CC) atomicAdd(&g_Q3[t-CC],(double)sq[t-CC]);
}

// compose bn_nbr and bn_post analytically:
// mean(bn_nbr(x)) = b_nbr exactly; var = g_nbr^2 * v/(v+eps) exactly.
__global__ void k_stats3(const float* __restrict__ gn, const float* __restrict__ bn,
                         const float* __restrict__ gp, const float* __restrict__ bp){
    int c=threadIdx.x; if(c>=CC) return;
    double m = g_S3[c]/(double)NP;
    double v = g_Q3[c]/(double)NP - m*m;
    double rs = rsqrt(v + BNEPS);
    double gnd = (double)gn[c];
    double vy = gnd*gnd*v*rs*rs;
    double rs2 = rsqrt(vy + BNEPS);
    double sc = gnd*rs*rs2*(double)gp[c];
    g_sc3[c]=(float)sc;
    g_sh3[c]=(float)((double)bp[c] - m*sc);
    (void)bn; // b_nbr cancels exactly in the composition
}

__global__ void k_weff(const float* __restrict__ wp){
    int c=blockIdx.x, h=threadIdx.x;
    g_Weff[c*HD+h] = g_sc3[c]*wp[c*HD+h];
}

__global__ void k_bias(const float* __restrict__ wp){
    int h=threadIdx.x;
    float b=0.f;
    for(int c=0;c<CC;c++) b += g_sh3[c]*wp[c*HD+h];
    g_bias[h]=b;
}

// out[n][h] = pooled[n] . Weff[:,h] + bias[h]   (200000 x 64 x 256)
__global__ void __launch_bounds__(256) k_pass4(float* __restrict__ out){
    __shared__ __align__(16) float sW[CC*128];
    __shared__ float sP[32*CC];
    __shared__ float sB[128];
    int t=threadIdx.x;
    int n0 = blockIdx.x*32;
    int hb = blockIdx.y*128;
    for(int i=t;i<CC*128;i+=256){ int c=i>>7, hh=i&127; sW[i]=g_Weff[c*HD+hb+hh]; }
    for(int i=t;i<32*CC;i+=256) sP[i]=g_pooled[n0*CC + i];
    if(t<128) sB[t]=g_bias[hb+t];
    __syncthreads();
    int pi=t>>5, hj=t&31;
    u64 acc[4][2];
    #pragma unroll
    for(int pp=0;pp<4;pp++){acc[pp][0]=0ull;acc[pp][1]=0ull;}
    const float* pbase = sP + (pi*4)*CC;
    #pragma unroll 4
    for(int c=0;c<CC;c++){
        ulonglong2 w = *reinterpret_cast<const ulonglong2*>(sW + c*128 + hj*4);
        #pragma unroll
        for(int pp=0;pp<4;pp++){
            float v = pbase[pp*CC + c];
            u64 vp = pk2(v,v);
            acc[pp][0]=f2fma(vp,w.x,acc[pp][0]);
            acc[pp][1]=f2fma(vp,w.y,acc[pp][1]);
        }
    }
    float b0=sB[hj*4], b1=sB[hj*4+1], b2=sB[hj*4+2], b3=sB[hj*4+3];
    #pragma unroll
    for(int pp=0;pp<4;pp++){
        float v0,v1,v2,v3; up2(acc[pp][0],v0,v1); up2(acc[pp][1],v2,v3);
        float4 o; o.x=v0+b0; o.y=v1+b1; o.z=v2+b2; o.w=v3+b3;
        int np = n0 + pi*4 + pp;
        *reinterpret_cast<float4*>(out + np*HD + hb + hj*4) = o;
    }
}

extern "C" void kernel_launch(void* const* d_in, const int* in_sizes, int n_in,
                              void* d_out, int out_size){
    const float* p  = (const float*)d_in[0];
    const float* f  = (const float*)d_in[1];
    const int*   gi = (const int*)  d_in[2];
    const float* w1 = (const float*)d_in[3];
    const float* g1 = (const float*)d_in[4];
    const float* b1 = (const float*)d_in[5];
    const float* w2 = (const float*)d_in[6];
    const float* g2 = (const float*)d_in[7];
    const float* b2 = (const float*)d_in[8];
    const float* w3 = (const float*)d_in[9];
    const float* gn = (const float*)d_in[10];
    const float* bn = (const float*)d_in[11];
    const float* gp = (const float*)d_in[12];
    const float* bp = (const float*)d_in[13];
    const float* wp = (const float*)d_in[14];
    float* out = (float*)d_out;
    (void)in_sizes; (void)n_in; (void)out_size;

    k_init  <<<1, CC>>>();
    k_pass1 <<<1184, 256>>>(p, f, gi, w1);
    k_stats1<<<1, H1C>>>(g1, b1);
    k_pass2 <<<1184, 256>>>(p, f, gi, w1, w2);
    k_stats2<<<1, H2C>>>(g2, b2);
    k_pass3 <<<NP/8, 128>>>(p, f, gi, w1, w2, w3);
    k_red3  <<<592, 256>>>();
    k_stats3<<<1, CC>>>(gn, bn, gp, bp);
    k_weff  <<<CC, HD>>>(wp);
    k_bias  <<<1, HD>>>(wp);
    k_pass4 <<<dim3(NP/32, 2), 256>>>(out);
}

// round 2
// speedup vs baseline: 1.3435x; 1.3435x over previous
#include <cuda_runtime.h>

#define NP 200000
#define KN 16
#define MR 3200000
#define H1C 16
#define H2C 32
#define CC 64
#define HD 256
#define BNEPS 1e-5

// ---------------- scratch (no allocations allowed) ----------------
__device__ double g_MX[7],  g_MXX[28];    // sum x, sum x x^T (triangle)
__device__ double g_MH[16], g_MHH[136];   // sum h1, sum h1 h1^T (triangle)
__device__ double g_S3[CC], g_Q3[CC];
__device__ float  g_par1[2*H1C];
__device__ float  g_par2[2*H2C];
__device__ float  g_sc3[CC], g_sh3[CC];
__device__ float  g_pooled[NP*CC];
__device__ float  g_Weff[CC*HD];
__device__ float  g_bias[HD];

typedef unsigned long long u64;

// ---------------- packed f32x2 helpers ----------------
__device__ __forceinline__ u64 pk2(float lo, float hi){
    u64 r; asm("mov.b64 %0, {%1, %2};" : "=l"(r) : "f"(lo), "f"(hi)); return r;
}
__device__ __forceinline__ void up2(u64 v, float &lo, float &hi){
    asm("mov.b64 {%0, %1}, %2;" : "=f"(lo), "=f"(hi) : "l"(v));
}
__device__ __forceinline__ u64 f2fma(u64 a, u64 b, u64 c){
    u64 r; asm("fma.rn.f32x2 %0, %1, %2, %3;" : "=l"(r) : "l"(a), "l"(b), "l"(c)); return r;
}

__device__ __forceinline__ float gelu(float v){
    return 0.5f*v*(1.0f + erff(v*0.70710678118654752f));
}

__device__ __forceinline__ void gatherx(float x[7], const float* __restrict__ p,
                                        const float* __restrict__ f, int n, int idx){
    float px = p[3*n], py = p[3*n+1], pz = p[3*n+2];
    x[0] = p[3*idx]   - px;
    x[1] = p[3*idx+1] - py;
    x[2] = p[3*idx+2] - pz;
    float4 fv = *reinterpret_cast<const float4*>(f + 4*idx);
    x[3]=fv.x; x[4]=fv.y; x[5]=fv.z; x[6]=fv.w;
}

// a = x @ w1   (w1 shared, row-major [7][16])
__device__ __forceinline__ void lin1(const float x[7], const float* sw1, float a[H1C]){
    u64 acc[8];
    #pragma unroll
    for(int u=0;u<8;u++) acc[u]=0ull;
    #pragma unroll
    for(int i=0;i<7;i++){
        u64 xp = pk2(x[i], x[i]);
        const u64* w = reinterpret_cast<const u64*>(sw1 + i*H1C);
        #pragma unroll
        for(int u=0;u<8;u++) acc[u] = f2fma(xp, w[u], acc[u]);
    }
    #pragma unroll
    for(int u=0;u<8;u++) up2(acc[u], a[2*u], a[2*u+1]);
}

// a = h @ w2   (w2 shared, row-major [16][32])
__device__ __forceinline__ void lin2(const float h[H1C], const float* sw2, float a[H2C]){
    u64 acc[16];
    #pragma unroll
    for(int u=0;u<16;u++) acc[u]=0ull;
    #pragma unroll
    for(int i=0;i<H1C;i++){
        u64 hp = pk2(h[i], h[i]);
        const u64* w = reinterpret_cast<const u64*>(sw2 + i*H2C);
        #pragma unroll
        for(int u=0;u<16;u++) acc[u] = f2fma(hp, w[u], acc[u]);
    }
    #pragma unroll
    for(int u=0;u<16;u++) up2(acc[u], a[2*u], a[2*u+1]);
}

__device__ __forceinline__ float wred(float v){
    #pragma unroll
    for(int o=16;o>0;o>>=1) v += __shfl_down_sync(0xffffffffu, v, o);
    return v;
}

// ---------------- kernels ----------------
__global__ void k_init(){
    int t = threadIdx.x;
    if(t<7)   g_MX[t]=0.0;
    if(t<28)  g_MXX[t]=0.0;
    if(t<16)  g_MH[t]=0.0;
    if(t<136) g_MHH[t]=0.0;
    if(t<CC){ g_S3[t]=0.0; g_Q3[t]=0.0; }
}

// ---- pass1: moments of x (7-dim) over all 3.2M rows. 1250 blocks x 256, 10 rows/thread exact.
__global__ void __launch_bounds__(256) k_pass1m(const float* __restrict__ p,
    const float* __restrict__ f, const int* __restrict__ gi){
    const int T = 1250*256;
    int t = blockIdx.x*blockDim.x + threadIdx.x;
    float sx[7], sxx[28];
    #pragma unroll
    for(int i=0;i<7;i++) sx[i]=0.f;
    #pragma unroll
    for(int i=0;i<28;i++) sxx[i]=0.f;

    int r = t;
    int idxn = gi[r];
    float xb[7];
    gatherx(xb, p, f, r>>4, idxn);
    idxn = gi[r+T];
    #pragma unroll 1
    for(int it=0; it<10; it++){
        float x[7];
        #pragma unroll
        for(int u=0;u<7;u++) x[u]=xb[u];
        int rn = r + T;
        if(it < 9){
            gatherx(xb, p, f, rn>>4, idxn);
            if(it < 8) idxn = gi[rn+T];
        }
        r = rn;
        int c=0;
        #pragma unroll
        for(int i=0;i<7;i++){
            sx[i]+=x[i];
            #pragma unroll
            for(int k=i;k<7;k++) sxx[c++] += x[i]*x[k];
        }
    }
    __shared__ float rs[7], rm[28];
    int tt = threadIdx.x;
    if(tt<7) rs[tt]=0.f;
    if(tt<28) rm[tt]=0.f;
    __syncthreads();
    int lane = tt & 31;
    #pragma unroll
    for(int i=0;i<7;i++){ float v=wred(sx[i]); if(lane==0) atomicAdd(&rs[i],v); }
    #pragma unroll
    for(int i=0;i<28;i++){ float v=wred(sxx[i]); if(lane==0) atomicAdd(&rm[i],v); }
    __syncthreads();
    if(tt<7)  atomicAdd(&g_MX[tt],  (double)rs[tt]);
    if(tt<28) atomicAdd(&g_MXX[tt], (double)rm[tt]);
}

__device__ __forceinline__ int tri7(int i, int k){
    if(i>k){int s=i;i=k;k=s;}
    return i*7 - (i*(i-1))/2 + (k-i);
}
__device__ __forceinline__ int tri16(int i, int k){
    if(i>k){int s=i;i=k;k=s;}
    return i*16 - (i*(i-1))/2 + (k-i);
}

__global__ void k_stats1(const float* __restrict__ w1, const float* __restrict__ g1,
                         const float* __restrict__ b1){
    int j = threadIdx.x;
    if(j >= H1C) return;
    double inv = 1.0/(double)MR;
    double m = 0.0, es = 0.0;
    for(int i=0;i<7;i++){
        double wij = (double)w1[i*H1C+j];
        m += g_MX[i]*inv*wij;
        for(int k=0;k<7;k++)
            es += g_MXX[tri7(i,k)]*inv * wij * (double)w1[k*H1C+j];
    }
    double v = es - m*m;
    double rs = rsqrt(v + BNEPS);
    float sc = (float)((double)g1[j] * rs);
    g_par1[j] = sc;
    g_par1[H1C+j] = b1[j] - (float)m * sc;
}

// ---- pass2: moments of h1 = gelu(bn1(x@w1)). 625 blocks x 256, 20 rows/thread exact.
__global__ void __launch_bounds__(256) k_pass2m(const float* __restrict__ p,
    const float* __restrict__ f, const int* __restrict__ gi, const float* __restrict__ w1){
    const int T = 625*256;
    __shared__ __align__(16) float sw1[7*H1C];
    __shared__ float sp1[2*H1C];
    int tt = threadIdx.x;
    if(tt < 7*H1C) sw1[tt]=w1[tt];
    if(tt < 2*H1C) sp1[tt]=g_par1[tt];
    __syncthreads();

    float sh[16], mh[136];
    #pragma unroll
    for(int i=0;i<16;i++) sh[i]=0.f;
    #pragma unroll
    for(int i=0;i<136;i++) mh[i]=0.f;

    int t = blockIdx.x*blockDim.x + tt;
    int r = t;
    int idxn = gi[r];
    float xb[7];
    gatherx(xb, p, f, r>>4, idxn);
    idxn = gi[r+T];
    #pragma unroll 1
    for(int it=0; it<20; it++){
        float x[7];
        #pragma unroll
        for(int u=0;u<7;u++) x[u]=xb[u];
        int rn = r + T;
        if(it < 19){
            gatherx(xb, p, f, rn>>4, idxn);
            if(it < 18) idxn = gi[rn+T];
        }
        r = rn;
        float a1[H1C]; lin1(x, sw1, a1);
        float h1[H1C];
        #pragma unroll
        for(int j=0;j<H1C;j++) h1[j] = gelu(a1[j]*sp1[j] + sp1[H1C+j]);
        int c=0;
        #pragma unroll
        for(int i=0;i<16;i++){
            sh[i]+=h1[i];
            #pragma unroll
            for(int k=i;k<16;k++) mh[c++] += h1[i]*h1[k];
        }
    }
    __shared__ float rs[16], rm[136];
    if(tt<16) rs[tt]=0.f;
    if(tt<136) rm[tt]=0.f;
    __syncthreads();
    int lane = tt & 31;
    #pragma unroll
    for(int i=0;i<16;i++){ float v=wred(sh[i]); if(lane==0) atomicAdd(&rs[i],v); }
    #pragma unroll
    for(int i=0;i<136;i++){ float v=wred(mh[i]); if(lane==0) atomicAdd(&rm[i],v); }
    __syncthreads();
    if(tt<16)  atomicAdd(&g_MH[tt],  (double)rs[tt]);
    if(tt<136) atomicAdd(&g_MHH[tt], (double)rm[tt]);
}

__global__ void k_stats2(const float* __restrict__ w2, const float* __restrict__ g2,
                         const float* __restrict__ b2){
    int j = threadIdx.x;
    if(j >= H2C) return;
    double inv = 1.0/(double)MR;
    double m = 0.0, es = 0.0;
    for(int i=0;i<16;i++){
        double wij = (double)w2[i*H2C+j];
        m += g_MH[i]*inv*wij;
        for(int k=0;k<16;k++)
            es += g_MHH[tri16(i,k)]*inv * wij * (double)w2[k*H2C+j];
    }
    double v = es - m*m;
    double rs = rsqrt(v + BNEPS);
    float sc = (float)((double)g2[j] * rs);
    g_par2[j] = sc;
    g_par2[H2C+j] = b2[j] - (float)m * sc;
}

// ---- pass3: full MLP -> a3 -> max over K -> pooled, with fused pooled stats.
// 625 persistent blocks x 128 threads; 40 tiles (of 8 points) each, exact.
#define P3G 625
#define P3T 40
__global__ void __launch_bounds__(128) k_pass3(const float* __restrict__ p, const float* __restrict__ f,
    const int* __restrict__ gi, const float* __restrict__ w1, const float* __restrict__ w2,
    const float* __restrict__ w3){
    __shared__ __align__(16) float sw1[7*H1C];
    __shared__ __align__(16) float sw2[H1C*H2C];
    __shared__ __align__(16) float sw3[H2C*CC];
    __shared__ float sp1[2*H1C];
    __shared__ float sp2[2*H2C];
    __shared__ float h2s[128*33];
    __shared__ float ss[CC], sq[CC];
    int t = threadIdx.x;
    if(t < 7*H1C) sw1[t]=w1[t];
    if(t < 2*H1C) sp1[t]=g_par1[t];
    if(t < 2*H2C) sp2[t]=g_par2[t];
    if(t < CC){ ss[t]=0.f; sq[t]=0.f; }
    for(int i=t;i<H1C*H2C;i+=128) sw2[i]=w2[i];
    for(int i=t;i<H2C*CC;i+=128) sw3[i]=w3[i];
    __syncthreads();

    int pl = t>>4;          // local point 0..7 (both stages)
    int kk = t&15;          // neighbor (stage A) / channel group (stage B)
    int c0 = kk*4;

    float sreg[4], qreg[4];
    #pragma unroll
    for(int i=0;i<4;i++){ sreg[i]=0.f; qreg[i]=0.f; }

    int tile = blockIdx.x;
    // prologue: gather for tile, gi for tile+P3G
    int idxn = gi[(tile*8+pl)*16 + kk];
    float xb[7];
    gatherx(xb, p, f, tile*8+pl, idxn);
    idxn = gi[((tile+P3G)*8+pl)*16 + kk];

    #pragma unroll 1
    for(int it=0; it<P3T; it++){
        // ---- stage A: one thread per (point, neighbor) row
        float x[7];
        #pragma unroll
        for(int u=0;u<7;u++) x[u]=xb[u];
        float a1[H1C]; lin1(x, sw1, a1);
        float h1[H1C];
        #pragma unroll
        for(int j=0;j<H1C;j++) h1[j] = gelu(a1[j]*sp1[j] + sp1[H1C+j]);
        float a2[H2C]; lin2(h1, sw2, a2);
        float* hw = &h2s[t*33];
        #pragma unroll
        for(int j=0;j<H2C;j++) hw[j] = gelu(a2[j]*sp2[j] + sp2[H2C+j]);

        // ---- prefetch next tile (hidden behind stage B)
        int tilen = tile + P3G;
        if(it < P3T-1){
            gatherx(xb, p, f, tilen*8+pl, idxn);
            if(it < P3T-2) idxn = gi[((tilen+P3G)*8+pl)*16 + kk];
        }
        __syncthreads();

        // ---- stage B: thread = (point pl, channels c0..c0+3)
        float m0=-3.4e38f, m1=-3.4e38f, m2=-3.4e38f, m3=-3.4e38f;
        #pragma unroll 1
        for(int k=0;k<KN;k++){
            const float* hr = &h2s[(pl*KN + k)*33];
            u64 a01=0ull, a23=0ull;
            #pragma unroll
            for(int q=0;q<H2C;q++){
                u64 hp = pk2(hr[q], hr[q]);
                ulonglong2 w = *reinterpret_cast<const ulonglong2*>(sw3 + q*CC + c0);
                a01 = f2fma(hp, w.x, a01);
                a23 = f2fma(hp, w.y, a23);
            }
            float v0,v1,v2,v3; up2(a01,v0,v1); up2(a23,v2,v3);
            m0=fmaxf(m0,v0); m1=fmaxf(m1,v1); m2=fmaxf(m2,v2); m3=fmaxf(m3,v3);
        }
        int np = tile*8 + pl;
        float4 o; o.x=m0; o.y=m1; o.z=m2; o.w=m3;
        *reinterpret_cast<float4*>(g_pooled + np*CC + c0) = o;
        sreg[0]+=m0; qreg[0]+=m0*m0;
        sreg[1]+=m1; qreg[1]+=m1*m1;
        sreg[2]+=m2; qreg[2]+=m2*m2;
        sreg[3]+=m3; qreg[3]+=m3*m3;

        tile = tilen;
        __syncthreads();   // h2s reuse
    }

    // fused pooled stats: smem combine then one double atomic per channel
    #pragma unroll
    for(int i=0;i<4;i++){
        atomicAdd(&ss[c0+i], sreg[i]);
        atomicAdd(&sq[c0+i], qreg[i]);
    }
    __syncthreads();
    if(t < CC)       atomicAdd(&g_S3[t], (double)ss[t]);
    else if(t < 2*CC) atomicAdd(&g_Q3[t-CC], (double)sq[t-CC]);
}

// compose bn_nbr and bn_post analytically
__global__ void k_stats3(const float* __restrict__ gn, const float* __restrict__ bn,
                         const float* __restrict__ gp, const float* __restrict__ bp){
    int c=threadIdx.x; if(c>=CC) return;
    double m = g_S3[c]/(double)NP;
    double v = g_Q3[c]/(double)NP - m*m;
    double rs = rsqrt(v + BNEPS);
    double gnd = (double)gn[c];
    double vy = gnd*gnd*v*rs*rs;
    double rs2 = rsqrt(vy + BNEPS);
    double sc = gnd*rs*rs2*(double)gp[c];
    g_sc3[c]=(float)sc;
    g_sh3[c]=(float)((double)bp[c] - m*sc);
    (void)bn;
}

__global__ void k_weff(const float* __restrict__ wp){
    int c=blockIdx.x, h=threadIdx.x;
    g_Weff[c*HD+h] = g_sc3[c]*wp[c*HD+h];
}

__global__ void k_bias(const float* __restrict__ wp){
    int h=threadIdx.x;
    float b=0.f;
    for(int c=0;c<CC;c++) b += g_sh3[c]*wp[c*HD+h];
    g_bias[h]=b;
}

// out[n][h] = pooled[n] . Weff[:,h] + bias[h]
__global__ void __launch_bounds__(256) k_pass4(float* __restrict__ out){
    __shared__ __align__(16) float sW[CC*128];
    __shared__ float sP[32*CC];
    __shared__ float sB[128];
    int t=threadIdx.x;
    int n0 = blockIdx.x*32;
    int hb = blockIdx.y*128;
    for(int i=t;i<CC*128;i+=256){ int c=i>>7, hh=i&127; sW[i]=g_Weff[c*HD+hb+hh]; }
    for(int i=t;i<32*CC;i+=256) sP[i]=g_pooled[n0*CC + i];
    if(t<128) sB[t]=g_bias[hb+t];
    __syncthreads();
    int pi=t>>5, hj=t&31;
    u64 acc[4][2];
    #pragma unroll
    for(int pp=0;pp<4;pp++){acc[pp][0]=0ull;acc[pp][1]=0ull;}
    const float* pbase = sP + (pi*4)*CC;
    #pragma unroll 4
    for(int c=0;c<CC;c++){
        ulonglong2 w = *reinterpret_cast<const ulonglong2*>(sW + c*128 + hj*4);
        #pragma unroll
        for(int pp=0;pp<4;pp++){
            float v = pbase[pp*CC + c];
            u64 vp = pk2(v,v);
            acc[pp][0]=f2fma(vp,w.x,acc[pp][0]);
            acc[pp][1]=f2fma(vp,w.y,acc[pp][1]);
        }
    }
    float b0=sB[hj*4], b1=sB[hj*4+1], b2=sB[hj*4+2], b3=sB[hj*4+3];
    #pragma unroll
    for(int pp=0;pp<4;pp++){
        float v0,v1,v2,v3; up2(acc[pp][0],v0,v1); up2(acc[pp][1],v2,v3);
        float4 o; o.x=v0+b0; o.y=v1+b1; o.z=v2+b2; o.w=v3+b3;
        int np = n0 + pi*4 + pp;
        *reinterpret_cast<float4*>(out + np*HD + hb + hj*4) = o;
    }
}

extern "C" void kernel_launch(void* const* d_in, const int* in_sizes, int n_in,
                              void* d_out, int out_size){
    const float* p  = (const float*)d_in[0];
    const float* f  = (const float*)d_in[1];
    const int*   gi = (const int*)  d_in[2];
    const float* w1 = (const float*)d_in[3];
    const float* g1 = (const float*)d_in[4];
    const float* b1 = (const float*)d_in[5];
    const float* w2 = (const float*)d_in[6];
    const float* g2 = (const float*)d_in[7];
    const float* b2 = (const float*)d_in[8];
    const float* w3 = (const float*)d_in[9];
    const float* gn = (const float*)d_in[10];
    const float* bn = (const float*)d_in[11];
    const float* gp = (const float*)d_in[12];
    const float* bp = (const float*)d_in[13];
    const float* wp = (const float*)d_in[14];
    float* out = (float*)d_out;
    (void)in_sizes; (void)n_in; (void)out_size;

    k_init   <<<1, 256>>>();
    k_pass1m <<<1250, 256>>>(p, f, gi);
    k_stats1 <<<1, H1C>>>(w1, g1, b1);
    k_pass2m <<<625, 256>>>(p, f, gi, w1);
    k_stats2 <<<1, H2C>>>(w2, g2, b2);
    k_pass3  <<<P3G, 128>>>(p, f, gi, w1, w2, w3);
    k_stats3 <<<1, CC>>>(gn, bn, gp, bp);
    k_weff   <<<CC, HD>>>(wp);
    k_bias   <<<1, HD>>>(wp);
    k_pass4  <<<dim3(NP/32, 2), 256>>>(out);
}

// round 3
// speedup vs baseline: 1.6050x; 1.1946x over previous
#include <cuda_runtime.h>

#define NP 200000
#define KN 16
#define MR 3200000
#define H1C 16
#define H2C 32
#define CC 64
#define HD 256
#define BNEPS 1e-5

// ---------------- scratch (no allocations allowed) ----------------
__device__ double g_MX[7],  g_MXX[28];    // sum x, sum x x^T (triangle)
__device__ double g_MH[16], g_MHH[136];   // sum h1, sum h1 h1^T (triangle)
__device__ double g_S3[CC], g_Q3[CC];
__device__ float  g_par1[2*H1C];
__device__ float  g_par2[2*H2C];
__device__ float  g_sc3[CC], g_sh3[CC];
__device__ float4 g_xc4[2*MR];            // cached gathered rows (8 floats/row), 102.4MB
__device__ float  g_pooled[NP*CC];        // 51.2MB
__device__ float  g_Weff[CC*HD];
__device__ float  g_bias[HD];

typedef unsigned long long u64;

// ---------------- packed f32x2 helpers ----------------
__device__ __forceinline__ u64 pk2(float lo, float hi){
    u64 r; asm("mov.b64 %0, {%1, %2};" : "=l"(r) : "f"(lo), "f"(hi)); return r;
}
__device__ __forceinline__ void up2(u64 v, float &lo, float &hi){
    asm("mov.b64 {%0, %1}, %2;" : "=f"(lo), "=f"(hi) : "l"(v));
}
__device__ __forceinline__ u64 f2fma(u64 a, u64 b, u64 c){
    u64 r; asm("fma.rn.f32x2 %0, %1, %2, %3;" : "=l"(r) : "l"(a), "l"(b), "l"(c)); return r;
}

__device__ __forceinline__ float gelu(float v){
    return 0.5f*v*(1.0f + erff(v*0.70710678118654752f));
}

__device__ __forceinline__ void gatherx(float x[7], const float* __restrict__ p,
                                        const float* __restrict__ f, int n, int idx){
    float px = p[3*n], py = p[3*n+1], pz = p[3*n+2];
    x[0] = p[3*idx]   - px;
    x[1] = p[3*idx+1] - py;
    x[2] = p[3*idx+2] - pz;
    float4 fv = *reinterpret_cast<const float4*>(f + 4*idx);
    x[3]=fv.x; x[4]=fv.y; x[5]=fv.z; x[6]=fv.w;
}

// a = x @ w1   (w1 shared, row-major [7][16])
__device__ __forceinline__ void lin1(const float x[7], const float* sw1, float a[H1C]){
    u64 acc[8];
    #pragma unroll
    for(int u=0;u<8;u++) acc[u]=0ull;
    #pragma unroll
    for(int i=0;i<7;i++){
        u64 xp = pk2(x[i], x[i]);
        const u64* w = reinterpret_cast<const u64*>(sw1 + i*H1C);
        #pragma unroll
        for(int u=0;u<8;u++) acc[u] = f2fma(xp, w[u], acc[u]);
    }
    #pragma unroll
    for(int u=0;u<8;u++) up2(acc[u], a[2*u], a[2*u+1]);
}

// a = h @ w2   (w2 shared, row-major [16][32])
__device__ __forceinline__ void lin2(const float h[H1C], const float* sw2, float a[H2C]){
    u64 acc[16];
    #pragma unroll
    for(int u=0;u<16;u++) acc[u]=0ull;
    #pragma unroll
    for(int i=0;i<H1C;i++){
        u64 hp = pk2(h[i], h[i]);
        const u64* w = reinterpret_cast<const u64*>(sw2 + i*H2C);
        #pragma unroll
        for(int u=0;u<16;u++) acc[u] = f2fma(hp, w[u], acc[u]);
    }
    #pragma unroll
    for(int u=0;u<16;u++) up2(acc[u], a[2*u], a[2*u+1]);
}

__device__ __forceinline__ float wred(float v){
    #pragma unroll
    for(int o=16;o>0;o>>=1) v += __shfl_down_sync(0xffffffffu, v, o);
    return v;
}

// ---------------- kernels ----------------
__global__ void k_init(){
    int t = threadIdx.x;
    if(t<7)   g_MX[t]=0.0;
    if(t<28)  g_MXX[t]=0.0;
    if(t<16)  g_MH[t]=0.0;
    if(t<136) g_MHH[t]=0.0;
    if(t<CC){ g_S3[t]=0.0; g_Q3[t]=0.0; }
}

// ---- pass1: gather x, write xc, accumulate x moments. 1250 blocks x 256, 10 rows exact.
__global__ void __launch_bounds__(256) k_pass1m(const float* __restrict__ p,
    const float* __restrict__ f, const int* __restrict__ gi){
    const int T = 1250*256;
    int t = blockIdx.x*blockDim.x + threadIdx.x;
    float sx[7], sxx[28];
    #pragma unroll
    for(int i=0;i<7;i++) sx[i]=0.f;
    #pragma unroll
    for(int i=0;i<28;i++) sxx[i]=0.f;

    #pragma unroll 1
    for(int g=0; g<2; g++){
        int r0 = t + g*(5*T);
        int idx[5];
        #pragma unroll
        for(int j=0;j<5;j++) idx[j] = gi[r0 + j*T];
        float xb[5][7];
        #pragma unroll
        for(int j=0;j<5;j++) gatherx(xb[j], p, f, (r0 + j*T)>>4, idx[j]);
        #pragma unroll
        for(int j=0;j<5;j++){
            int c=0;
            #pragma unroll
            for(int i=0;i<7;i++){
                sx[i] += xb[j][i];
                #pragma unroll
                for(int k=i;k<7;k++) sxx[c++] += xb[j][i]*xb[j][k];
            }
            int r = r0 + j*T;
            float4 A; A.x=xb[j][0]; A.y=xb[j][1]; A.z=xb[j][2]; A.w=xb[j][3];
            float4 B; B.x=xb[j][4]; B.y=xb[j][5]; B.z=xb[j][6]; B.w=0.f;
            g_xc4[2*r]   = A;
            g_xc4[2*r+1] = B;
        }
    }
    __shared__ float rs[7], rm[28];
    int tt = threadIdx.x;
    if(tt<7) rs[tt]=0.f;
    if(tt<28) rm[tt]=0.f;
    __syncthreads();
    int lane = tt & 31;
    #pragma unroll
    for(int i=0;i<7;i++){ float v=wred(sx[i]); if(lane==0) atomicAdd(&rs[i],v); }
    #pragma unroll
    for(int i=0;i<28;i++){ float v=wred(sxx[i]); if(lane==0) atomicAdd(&rm[i],v); }
    __syncthreads();
    if(tt<7)  atomicAdd(&g_MX[tt],  (double)rs[tt]);
    if(tt<28) atomicAdd(&g_MXX[tt], (double)rm[tt]);
}

__device__ __forceinline__ int tri7(int i, int k){
    if(i>k){int s=i;i=k;k=s;}
    return i*7 - (i*(i-1))/2 + (k-i);
}
__device__ __forceinline__ int tri16(int i, int k){
    if(i>k){int s=i;i=k;k=s;}
    return i*16 - (i*(i-1))/2 + (k-i);
}

__global__ void k_stats1(const float* __restrict__ w1, const float* __restrict__ g1,
                         const float* __restrict__ b1){
    int j = threadIdx.x;
    if(j >= H1C) return;
    double inv = 1.0/(double)MR;
    double m = 0.0, es = 0.0;
    for(int i=0;i<7;i++){
        double wij = (double)w1[i*H1C+j];
        m += g_MX[i]*inv*wij;
        for(int k=0;k<7;k++)
            es += g_MXX[tri7(i,k)]*inv * wij * (double)w1[k*H1C+j];
    }
    double v = es - m*m;
    double rs = rsqrt(v + BNEPS);
    float sc = (float)((double)g1[j] * rs);
    g_par1[j] = sc;
    g_par1[H1C+j] = b1[j] - (float)m * sc;
}

// ---- pass2: stream xc, h1 = gelu(bn1(x@w1)), lane-pair split triangle moments.
// 625 blocks x 256, 20 rows/thread exact.
__global__ void __launch_bounds__(256) k_pass2m(const float* __restrict__ w1){
    const int T = 625*256;
    __shared__ __align__(16) float sw1[7*H1C];
    __shared__ float sp1[2*H1C];
    int tt = threadIdx.x;
    if(tt < 7*H1C) sw1[tt]=w1[tt];
    if(tt < 2*H1C) sp1[tt]=g_par1[tt];
    __syncthreads();
    int lane = tt & 31;
    int par  = lane & 1;

    float sh[16], mh[68];
    #pragma unroll
    for(int i=0;i<16;i++) sh[i]=0.f;
    #pragma unroll
    for(int i=0;i<68;i++) mh[i]=0.f;

    int t = blockIdx.x*blockDim.x + tt;
    int r = t;
    float4 A = g_xc4[2*r], B = g_xc4[2*r+1];
    #pragma unroll 1
    for(int it=0; it<20; it++){
        float x[7] = {A.x,A.y,A.z,A.w,B.x,B.y,B.z};
        int rn = r + T;
        if(it < 19){ A = g_xc4[2*rn]; B = g_xc4[2*rn+1]; }
        r = rn;
        float a1[H1C]; lin1(x, sw1, a1);
        float h1[H1C];
        #pragma unroll
        for(int j=0;j<H1C;j++) h1[j] = gelu(a1[j]*sp1[j] + sp1[H1C+j]);
        float hp[H1C];
        #pragma unroll
        for(int j=0;j<H1C;j++) hp[j] = __shfl_xor_sync(0xffffffffu, h1[j], 1);
        #pragma unroll
        for(int j=0;j<H1C;j++) sh[j] += h1[j];
        // lane-pair split of the 136-entry triangle (sum over both rows is
        // symmetric in (h1,hp), so both parities use the unordered pair)
        if(par==0){
            int c=0;
            #pragma unroll
            for(int i=0;i<16;i++)
                #pragma unroll
                for(int k=i;k<16;k++){
                    if(c<68) mh[c] += h1[i]*h1[k] + hp[i]*hp[k];
                    c++;
                }
        } else {
            int c=0;
            #pragma unroll
            for(int i=0;i<16;i++)
                #pragma unroll
                for(int k=i;k<16;k++){
                    if(c>=68) mh[c-68] += h1[i]*h1[k] + hp[i]*hp[k];
                    c++;
                }
        }
    }
    __shared__ float rs[16], rm[136];
    if(tt<16) rs[tt]=0.f;
    if(tt<136) rm[tt]=0.f;
    __syncthreads();
    #pragma unroll
    for(int i=0;i<16;i++){ float v=wred(sh[i]); if(lane==0) atomicAdd(&rs[i],v); }
    // same-parity tree reduce (offsets even -> stays within parity class)
    #pragma unroll
    for(int e=0;e<68;e++){
        float v = mh[e];
        v += __shfl_down_sync(0xffffffffu, v, 16);
        v += __shfl_down_sync(0xffffffffu, v, 8);
        v += __shfl_down_sync(0xffffffffu, v, 4);
        v += __shfl_down_sync(0xffffffffu, v, 2);
        mh[e] = v;
    }
    if(lane==0){
        #pragma unroll
        for(int e=0;e<68;e++) atomicAdd(&rm[e], mh[e]);
    } else if(lane==1){
        #pragma unroll
        for(int e=0;e<68;e++) atomicAdd(&rm[68+e], mh[e]);
    }
    __syncthreads();
    if(tt<16)  atomicAdd(&g_MH[tt],  (double)rs[tt]);
    if(tt<136) atomicAdd(&g_MHH[tt], (double)rm[tt]);
}

__global__ void k_stats2(const float* __restrict__ w2, const float* __restrict__ g2,
                         const float* __restrict__ b2){
    int j = threadIdx.x;
    if(j >= H2C) return;
    double inv = 1.0/(double)MR;
    double m = 0.0, es = 0.0;
    for(int i=0;i<16;i++){
        double wij = (double)w2[i*H2C+j];
        m += g_MH[i]*inv*wij;
        for(int k=0;k<16;k++)
            es += g_MHH[tri16(i,k)]*inv * wij * (double)w2[k*H2C+j];
    }
    double v = es - m*m;
    double rs = rsqrt(v + BNEPS);
    float sc = (float)((double)g2[j] * rs);
    g_par2[j] = sc;
    g_par2[H2C+j] = b2[j] - (float)m * sc;
}

// ---- pass3: stream xc -> full MLP -> a3 -> max over K -> pooled + fused stats.
#define P3G 625
#define P3T 40
__global__ void __launch_bounds__(128) k_pass3(const float* __restrict__ w1,
    const float* __restrict__ w2, const float* __restrict__ w3){
    __shared__ __align__(16) float sw1[7*H1C];
    __shared__ __align__(16) float sw2[H1C*H2C];
    __shared__ __align__(16) float sw3[H2C*CC];
    __shared__ float sp1[2*H1C];
    __shared__ float sp2[2*H2C];
    __shared__ float h2s[128*33];
    __shared__ float ss[CC], sq[CC];
    int t = threadIdx.x;
    if(t < 7*H1C) sw1[t]=w1[t];
    if(t < 2*H1C) sp1[t]=g_par1[t];
    if(t < 2*H2C) sp2[t]=g_par2[t];
    if(t < CC){ ss[t]=0.f; sq[t]=0.f; }
    for(int i=t;i<H1C*H2C;i+=128) sw2[i]=w2[i];
    for(int i=t;i<H2C*CC;i+=128) sw3[i]=w3[i];
    __syncthreads();

    int pl = t>>4;          // local point 0..7
    int c0 = (t&15)*4;      // channel group (stage B)

    float sreg[4], qreg[4];
    #pragma unroll
    for(int i=0;i<4;i++){ sreg[i]=0.f; qreg[i]=0.f; }

    int tile = blockIdx.x;
    float4 A = g_xc4[(tile*128 + t)*2];
    float4 B = g_xc4[(tile*128 + t)*2 + 1];

    #pragma unroll 1
    for(int it=0; it<P3T; it++){
        // ---- stage A: one thread per (point, neighbor) row
        float x[7] = {A.x,A.y,A.z,A.w,B.x,B.y,B.z};
        float a1[H1C]; lin1(x, sw1, a1);
        float h1[H1C];
        #pragma unroll
        for(int j=0;j<H1C;j++) h1[j] = gelu(a1[j]*sp1[j] + sp1[H1C+j]);
        float a2[H2C]; lin2(h1, sw2, a2);
        float* hw = &h2s[t*33];
        #pragma unroll
        for(int j=0;j<H2C;j++) hw[j] = gelu(a2[j]*sp2[j] + sp2[H2C+j]);

        // prefetch next tile's x (hidden behind stage B)
        int tilen = tile + P3G;
        if(it < P3T-1){
            A = g_xc4[(tilen*128 + t)*2];
            B = g_xc4[(tilen*128 + t)*2 + 1];
        }
        __syncthreads();

        // ---- stage B: thread = (point pl, channels c0..c0+3)
        float m0=-3.4e38f, m1=-3.4e38f, m2=-3.4e38f, m3=-3.4e38f;
        #pragma unroll 1
        for(int k=0;k<KN;k++){
            const float* hr = &h2s[(pl*KN + k)*33];
            u64 a01=0ull, a23=0ull;
            #pragma unroll
            for(int q=0;q<H2C;q++){
                u64 hp = pk2(hr[q], hr[q]);
                ulonglong2 w = *reinterpret_cast<const ulonglong2*>(sw3 + q*CC + c0);
                a01 = f2fma(hp, w.x, a01);
                a23 = f2fma(hp, w.y, a23);
            }
            float v0,v1,v2,v3; up2(a01,v0,v1); up2(a23,v2,v3);
            m0=fmaxf(m0,v0); m1=fmaxf(m1,v1); m2=fmaxf(m2,v2); m3=fmaxf(m3,v3);
        }
        int np = tile*8 + pl;
        float4 o; o.x=m0; o.y=m1; o.z=m2; o.w=m3;
        *reinterpret_cast<float4*>(g_pooled + np*CC + c0) = o;
        sreg[0]+=m0; qreg[0]+=m0*m0;
        sreg[1]+=m1; qreg[1]+=m1*m1;
        sreg[2]+=m2; qreg[2]+=m2*m2;
        sreg[3]+=m3; qreg[3]+=m3*m3;

        tile = tilen;
        __syncthreads();   // h2s reuse
    }

    #pragma unroll
    for(int i=0;i<4;i++){
        atomicAdd(&ss[c0+i], sreg[i]);
        atomicAdd(&sq[c0+i], qreg[i]);
    }
    __syncthreads();
    if(t < CC)        atomicAdd(&g_S3[t], (double)ss[t]);
    else if(t < 2*CC) atomicAdd(&g_Q3[t-CC], (double)sq[t-CC]);
}

// compose bn_nbr and bn_post analytically
__global__ void k_stats3(const float* __restrict__ gn, const float* __restrict__ bn,
                         const float* __restrict__ gp, const float* __restrict__ bp){
    int c=threadIdx.x; if(c>=CC) return;
    double m = g_S3[c]/(double)NP;
    double v = g_Q3[c]/(double)NP - m*m;
    double rs = rsqrt(v + BNEPS);
    double gnd = (double)gn[c];
    double vy = gnd*gnd*v*rs*rs;
    double rs2 = rsqrt(vy + BNEPS);
    double sc = gnd*rs*rs2*(double)gp[c];
    g_sc3[c]=(float)sc;
    g_sh3[c]=(float)((double)bp[c] - m*sc);
    (void)bn;
}

__global__ void k_weff(const float* __restrict__ wp){
    int c=blockIdx.x, h=threadIdx.x;
    g_Weff[c*HD+h] = g_sc3[c]*wp[c*HD+h];
}

__global__ void k_bias(const float* __restrict__ wp){
    int h=threadIdx.x;
    float b=0.f;
    for(int c=0;c<CC;c++) b += g_sh3[c]*wp[c*HD+h];
    g_bias[h]=b;
}

// out[n][h] = pooled[n] . Weff[:,h] + bias[h]   (200000 x 64 x 256)
// sPT transposed (stride 36, 16B aligned) -> conflict-free vector loads.
__global__ void __launch_bounds__(256) k_pass4(float* __restrict__ out){
    __shared__ __align__(16) float sW[CC*128];
    __shared__ __align__(16) float sPT[CC*36];
    __shared__ float sB[128];
    int t=threadIdx.x;
    int n0 = blockIdx.x*32;
    int hb = blockIdx.y*128;
    for(int i=t;i<CC*128;i+=256){ int c=i>>7, hh=i&127; sW[i]=g_Weff[c*HD+hb+hh]; }
    for(int i=t;i<32*CC;i+=256){ int c=i&63, pt=i>>6; sPT[c*36+pt]=g_pooled[(n0+pt)*CC + c]; }
    if(t<128) sB[t]=g_bias[hb+t];
    __syncthreads();
    int pi=t>>5, hj=t&31;
    u64 acc[4][2];
    #pragma unroll
    for(int pp=0;pp<4;pp++){acc[pp][0]=0ull;acc[pp][1]=0ull;}
    #pragma unroll 4
    for(int c=0;c<CC;c++){
        float4 pv = *reinterpret_cast<const float4*>(sPT + c*36 + pi*4);
        ulonglong2 w = *reinterpret_cast<const ulonglong2*>(sW + c*128 + hj*4);
        u64 v0 = pk2(pv.x,pv.x), v1 = pk2(pv.y,pv.y), v2 = pk2(pv.z,pv.z), v3 = pk2(pv.w,pv.w);
        acc[0][0]=f2fma(v0,w.x,acc[0][0]); acc[0][1]=f2fma(v0,w.y,acc[0][1]);
        acc[1][0]=f2fma(v1,w.x,acc[1][0]); acc[1][1]=f2fma(v1,w.y,acc[1][1]);
        acc[2][0]=f2fma(v2,w.x,acc[2][0]); acc[2][1]=f2fma(v2,w.y,acc[2][1]);
        acc[3][0]=f2fma(v3,w.x,acc[3][0]); acc[3][1]=f2fma(v3,w.y,acc[3][1]);
    }
    float b0=sB[hj*4], b1=sB[hj*4+1], b2=sB[hj*4+2], b3=sB[hj*4+3];
    #pragma unroll
    for(int pp=0;pp<4;pp++){
        float v0,v1,v2,v3; up2(acc[pp][0],v0,v1); up2(acc[pp][1],v2,v3);
        float4 o; o.x=v0+b0; o.y=v1+b1; o.z=v2+b2; o.w=v3+b3;
        int np = n0 + pi*4 + pp;
        *reinterpret_cast<float4*>(out + np*HD + hb + hj*4) = o;
    }
}

extern "C" void kernel_launch(void* const* d_in, const int* in_sizes, int n_in,
                              void* d_out, int out_size){
    const float* p  = (const float*)d_in[0];
    const float* f  = (const float*)d_in[1];
    const int*   gi = (const int*)  d_in[2];
    const float* w1 = (const float*)d_in[3];
    const float* g1 = (const float*)d_in[4];
    const float* b1 = (const float*)d_in[5];
    const float* w2 = (const float*)d_in[6];
    const float* g2 = (const float*)d_in[7];
    const float* b2 = (const float*)d_in[8];
    const float* w3 = (const float*)d_in[9];
    const float* gn = (const float*)d_in[10];
    const float* bn = (const float*)d_in[11];
    const float* gp = (const float*)d_in[12];
    const float* bp = (const float*)d_in[13];
    const float* wp = (const float*)d_in[14];
    float* out = (float*)d_out;
    (void)in_sizes; (void)n_in; (void)out_size;

    k_init   <<<1, 256>>>();
    k_pass1m <<<1250, 256>>>(p, f, gi);
    k_stats1 <<<1, H1C>>>(w1, g1, b1);
    k_pass2m <<<625, 256>>>(w1);
    k_stats2 <<<1, H2C>>>(w2, g2, b2);
    k_pass3  <<<P3G, 128>>>(w1, w2, w3);
    k_stats3 <<<1, CC>>>(gn, bn, gp, bp);
    k_weff   <<<CC, HD>>>(wp);
    k_bias   <<<1, HD>>>(wp);
    k_pass4  <<<dim3(NP/32, 2), 256>>>(out);
}

// round 7
// speedup vs baseline: 1.8488x; 1.1519x over previous
#include <cuda_runtime.h>

#define NP 200000
#define KN 16
#define MR 3200000
#define H1C 16
#define H2C 32
#define CC 64
#define HD 256
#define BNEPS 1e-5

// ---------------- scratch (no allocations allowed) ----------------
__device__ double g_MX[7],  g_MXX[28];    // sum x, sum x x^T (triangle)
__device__ double g_MH[16], g_MHH[136];   // sum h1, sum h1 h1^T (triangle)
__device__ double g_S3[CC], g_Q3[CC];
__device__ float  g_par1[2*H1C];
__device__ float  g_par2[2*H2C];
__device__ float4 g_xc4[2*MR];            // cached gathered rows (8 floats/row), 102.4MB
__device__ float  g_pooled[NP*CC];        // 51.2MB
__device__ float  g_Weff[CC*HD];
__device__ float  g_bias[HD];

typedef unsigned long long u64;

// ---------------- packed f32x2 helpers ----------------
__device__ __forceinline__ u64 pk2(float lo, float hi){
    u64 r; asm("mov.b64 %0, {%1, %2};" : "=l"(r) : "f"(lo), "f"(hi)); return r;
}
__device__ __forceinline__ void up2(u64 v, float &lo, float &hi){
    asm("mov.b64 {%0, %1}, %2;" : "=f"(lo), "=f"(hi) : "l"(v));
}
__device__ __forceinline__ u64 f2fma(u64 a, u64 b, u64 c){
    u64 r; asm("fma.rn.f32x2 %0, %1, %2, %3;" : "=l"(r) : "l"(a), "l"(b), "l"(c)); return r;
}
__device__ __forceinline__ u64 addx2(u64 a, u64 b){
    u64 r; asm("add.rn.f32x2 %0, %1, %2;" : "=l"(r) : "l"(a), "l"(b)); return r;
}
__device__ __forceinline__ u64 shfl64d(u64 v, int off, unsigned m){
    unsigned lo=(unsigned)v, hi=(unsigned)(v>>32);
    lo=__shfl_down_sync(m,lo,off); hi=__shfl_down_sync(m,hi,off);
    return ((u64)hi<<32)|(u64)lo;
}

__device__ __forceinline__ float gelu(float v){
    return 0.5f*v*(1.0f + erff(v*0.70710678118654752f));
}

__device__ __forceinline__ void gatherx(float x[7], const float* __restrict__ p,
                                        const float* __restrict__ f, int n, int idx){
    float px = p[3*n], py = p[3*n+1], pz = p[3*n+2];
    x[0] = p[3*idx]   - px;
    x[1] = p[3*idx+1] - py;
    x[2] = p[3*idx+2] - pz;
    float4 fv = *reinterpret_cast<const float4*>(f + 4*idx);
    x[3]=fv.x; x[4]=fv.y; x[5]=fv.z; x[6]=fv.w;
}

// a = x @ w1   (w1 shared, row-major [7][16])
__device__ __forceinline__ void lin1(const float x[7], const float* sw1, float a[H1C]){
    u64 acc[8];
    #pragma unroll
    for(int u=0;u<8;u++) acc[u]=0ull;
    #pragma unroll
    for(int i=0;i<7;i++){
        u64 xp = pk2(x[i], x[i]);
        const u64* w = reinterpret_cast<const u64*>(sw1 + i*H1C);
        #pragma unroll
        for(int u=0;u<8;u++) acc[u] = f2fma(xp, w[u], acc[u]);
    }
    #pragma unroll
    for(int u=0;u<8;u++) up2(acc[u], a[2*u], a[2*u+1]);
}

// a = h @ w2   (w2 shared, row-major [16][32])
__device__ __forceinline__ void lin2(const float h[H1C], const float* sw2, float a[H2C]){
    u64 acc[16];
    #pragma unroll
    for(int u=0;u<16;u++) acc[u]=0ull;
    #pragma unroll
    for(int i=0;i<H1C;i++){
        u64 hp = pk2(h[i], h[i]);
        const u64* w = reinterpret_cast<const u64*>(sw2 + i*H2C);
        #pragma unroll
        for(int u=0;u<16;u++) acc[u] = f2fma(hp, w[u], acc[u]);
    }
    #pragma unroll
    for(int u=0;u<16;u++) up2(acc[u], a[2*u], a[2*u+1]);
}

__device__ __forceinline__ float wred(float v){
    #pragma unroll
    for(int o=16;o>0;o>>=1) v += __shfl_down_sync(0xffffffffu, v, o);
    return v;
}

__device__ __forceinline__ int tri7(int i, int k){
    if(i>k){int s=i;i=k;k=s;}
    return i*7 - (i*(i-1))/2 + (k-i);
}
__device__ __forceinline__ int tri16(int i, int k){
    if(i>k){int s=i;i=k;k=s;}
    return i*16 - (i*(i-1))/2 + (k-i);
}

// ---------------- kernels ----------------
__global__ void k_init(){
    int t = threadIdx.x;
    if(t<7)   g_MX[t]=0.0;
    if(t<28)  g_MXX[t]=0.0;
    if(t<16)  g_MH[t]=0.0;
    if(t<136) g_MHH[t]=0.0;
    if(t<CC){ g_S3[t]=0.0; g_Q3[t]=0.0; }
}

// ---- pass1: gather x, write xc, accumulate x moments. 1250 blocks x 256, 10 rows exact.
__global__ void __launch_bounds__(256) k_pass1m(const float* __restrict__ p,
    const float* __restrict__ f, const int* __restrict__ gi){
    const int T = 1250*256;
    int t = blockIdx.x*blockDim.x + threadIdx.x;
    float sx[7], sxx[28];
    #pragma unroll
    for(int i=0;i<7;i++) sx[i]=0.f;
    #pragma unroll
    for(int i=0;i<28;i++) sxx[i]=0.f;

    #pragma unroll 1
    for(int g=0; g<2; g++){
        int r0 = t + g*(5*T);
        int idx[5];
        #pragma unroll
        for(int j=0;j<5;j++) idx[j] = gi[r0 + j*T];
        float xb[5][7];
        #pragma unroll
        for(int j=0;j<5;j++) gatherx(xb[j], p, f, (r0 + j*T)>>4, idx[j]);
        #pragma unroll
        for(int j=0;j<5;j++){
            int c=0;
            #pragma unroll
            for(int i=0;i<7;i++){
                sx[i] += xb[j][i];
                #pragma unroll
                for(int k=i;k<7;k++) sxx[c++] += xb[j][i]*xb[j][k];
            }
            int r = r0 + j*T;
            float4 A; A.x=xb[j][0]; A.y=xb[j][1]; A.z=xb[j][2]; A.w=xb[j][3];
            float4 B; B.x=xb[j][4]; B.y=xb[j][5]; B.z=xb[j][6]; B.w=0.f;
            g_xc4[2*r]   = A;
            g_xc4[2*r+1] = B;
        }
    }
    __shared__ float rs[7], rm[28];
    int tt = threadIdx.x;
    if(tt<7) rs[tt]=0.f;
    if(tt<28) rm[tt]=0.f;
    __syncthreads();
    int lane = tt & 31;
    #pragma unroll
    for(int i=0;i<7;i++){ float v=wred(sx[i]); if(lane==0) atomicAdd(&rs[i],v); }
    #pragma unroll
    for(int i=0;i<28;i++){ float v=wred(sxx[i]); if(lane==0) atomicAdd(&rm[i],v); }
    __syncthreads();
    if(tt<7)  atomicAdd(&g_MX[tt],  (double)rs[tt]);
    if(tt<28) atomicAdd(&g_MXX[tt], (double)rm[tt]);
}

__global__ void k_stats1(const float* __restrict__ w1, const float* __restrict__ g1,
                         const float* __restrict__ b1){
    int j = threadIdx.x;
    if(j >= H1C) return;
    double inv = 1.0/(double)MR;
    double m = 0.0, es = 0.0;
    for(int i=0;i<7;i++){
        double wij = (double)w1[i*H1C+j];
        m += g_MX[i]*inv*wij;
        for(int k=0;k<7;k++)
            es += g_MXX[tri7(i,k)]*inv * wij * (double)w1[k*H1C+j];
    }
    double v = es - m*m;
    double rs = rsqrt(v + BNEPS);
    float sc = (float)((double)g1[j] * rs);
    g_par1[j] = sc;
    g_par1[H1C+j] = b1[j] - (float)m * sc;
}

// ---- pass2: stream xc, h1 = gelu(bn1(x@w1)), lane-parity split + f32x2-packed triangle.
// 1250 blocks x 128 threads, 20 rows/thread exact.
// Even lanes: rows i=0,2,..,14 of the triangle (36 packed pairs).
// Odd lanes:  rows i=1,3,..,15 (8 solo diagonal-starts + 28 packed pairs).
__global__ void __launch_bounds__(128) k_pass2m(const float* __restrict__ w1){
    const int T = 1250*128;
    __shared__ __align__(16) float sw1[7*H1C];
    __shared__ float sp1[2*H1C];
    int tt = threadIdx.x;
    if(tt < 7*H1C) sw1[tt]=w1[tt];
    if(tt < 2*H1C) sp1[tt]=g_par1[tt];
    __syncthreads();
    int lane = tt & 31;
    int par  = lane & 1;

    float sh[16];
    u64 mh[36];
    float msolo[8];
    #pragma unroll
    for(int i=0;i<16;i++) sh[i]=0.f;
    #pragma unroll
    for(int i=0;i<36;i++) mh[i]=0ull;
    #pragma unroll
    for(int i=0;i<8;i++) msolo[i]=0.f;

    int t = blockIdx.x*blockDim.x + tt;
    int r = t;
    float4 A = g_xc4[2*r], B = g_xc4[2*r+1];
    #pragma unroll 1
    for(int it=0; it<20; it++){
        float x[7] = {A.x,A.y,A.z,A.w,B.x,B.y,B.z};
        int rn = r + T;
        if(it < 19){ A = g_xc4[2*rn]; B = g_xc4[2*rn+1]; }
        r = rn;
        float a1[H1C]; lin1(x, sw1, a1);
        float h1[H1C];
        #pragma unroll
        for(int j=0;j<H1C;j++) h1[j] = gelu(a1[j]*sp1[j] + sp1[H1C+j]);
        float hq[H1C];
        #pragma unroll
        for(int j=0;j<H1C;j++) hq[j] = __shfl_xor_sync(0xffffffffu, h1[j], 1);
        #pragma unroll
        for(int j=0;j<H1C;j++) sh[j] += h1[j];
        if(par==0){
            int e=0;
            #pragma unroll
            for(int i=0;i<16;i+=2){
                u64 hi1 = pk2(h1[i],h1[i]);
                u64 hi2 = pk2(hq[i],hq[i]);
                #pragma unroll
                for(int k=i;k<16;k+=2){
                    mh[e] = f2fma(hi1, pk2(h1[k],h1[k+1]), mh[e]);
                    mh[e] = f2fma(hi2, pk2(hq[k],hq[k+1]), mh[e]);
                    e++;
                }
            }
        } else {
            int e=0, s=0;
            #pragma unroll
            for(int i=1;i<16;i+=2){
                msolo[s] += h1[i]*h1[i] + hq[i]*hq[i];
                s++;
                u64 hi1 = pk2(h1[i],h1[i]);
                u64 hi2 = pk2(hq[i],hq[i]);
                #pragma unroll
                for(int k=i+1;k<15;k+=2){
                    mh[e] = f2fma(hi1, pk2(h1[k],h1[k+1]), mh[e]);
                    mh[e] = f2fma(hi2, pk2(hq[k],hq[k+1]), mh[e]);
                    e++;
                }
            }
        }
    }
    __shared__ float rs[16], rm[136];
    if(tt<16) rs[tt]=0.f;
    for(int i=tt;i<136;i+=128) rm[i]=0.f;
    __syncthreads();
    #pragma unroll
    for(int i=0;i<16;i++){ float v=wred(sh[i]); if(lane==0) atomicAdd(&rs[i],v); }
    if(par==0){
        const unsigned m0 = 0x55555555u;
        int e=0;
        #pragma unroll
        for(int i=0;i<16;i+=2){
            #pragma unroll
            for(int k=i;k<16;k+=2){
                u64 v = mh[e];
                v = addx2(v, shfl64d(v,16,m0));
                v = addx2(v, shfl64d(v, 8,m0));
                v = addx2(v, shfl64d(v, 4,m0));
                v = addx2(v, shfl64d(v, 2,m0));
                if(lane==0){
                    float lo,hi; up2(v,lo,hi);
                    atomicAdd(&rm[tri16(i,k)],   lo);
                    atomicAdd(&rm[tri16(i,k+1)], hi);
                }
                e++;
            }
        }
    } else {
        const unsigned m1 = 0xAAAAAAAAu;
        int e=0, s=0;
        #pragma unroll
        for(int i=1;i<16;i+=2){
            float v = msolo[s];
            v += __shfl_down_sync(m1, v, 16);
            v += __shfl_down_sync(m1, v, 8);
            v += __shfl_down_sync(m1, v, 4);
            v += __shfl_down_sync(m1, v, 2);
            if(lane==1) atomicAdd(&rm[tri16(i,i)], v);
            s++;
            #pragma unroll
            for(int k=i+1;k<15;k+=2){
                u64 vv = mh[e];
                vv = addx2(vv, shfl64d(vv,16,m1));
                vv = addx2(vv, shfl64d(vv, 8,m1));
                vv = addx2(vv, shfl64d(vv, 4,m1));
                vv = addx2(vv, shfl64d(vv, 2,m1));
                if(lane==1){
                    float lo,hi; up2(vv,lo,hi);
                    atomicAdd(&rm[tri16(i,k)],   lo);
                    atomicAdd(&rm[tri16(i,k+1)], hi);
                }
                e++;
            }
        }
    }
    __syncthreads();
    if(tt<16) atomicAdd(&g_MH[tt], (double)rs[tt]);
    for(int i=tt;i<136;i+=128) atomicAdd(&g_MHH[i], (double)rm[i]);
}

__global__ void k_stats2(const float* __restrict__ w2, const float* __restrict__ g2,
                         const float* __restrict__ b2){
    int j = threadIdx.x;
    if(j >= H2C) return;
    double inv = 1.0/(double)MR;
    double m = 0.0, es = 0.0;
    for(int i=0;i<16;i++){
        double wij = (double)w2[i*H2C+j];
        m += g_MH[i]*inv*wij;
        for(int k=0;k<16;k++)
            es += g_MHH[tri16(i,k)]*inv * wij * (double)w2[k*H2C+j];
    }
    double v = es - m*m;
    double rs = rsqrt(v + BNEPS);
    float sc = (float)((double)g2[j] * rs);
    g_par2[j] = sc;
    g_par2[H2C+j] = b2[j] - (float)m * sc;
}

// ---- pass3: stream xc -> full MLP -> a3 -> max over K -> pooled + fused stats.
// h2 stored TRANSPOSED in smem: h2sT[q][row], so stage B loads k-contiguous vectors
// and w3 is loaded once per q (not per (q,k)).
#define P3G 2500
#define P3T 10
__global__ void __launch_bounds__(128) k_pass3(const float* __restrict__ w1,
    const float* __restrict__ w2, const float* __restrict__ w3){
    __shared__ __align__(16) float sw1[7*H1C];
    __shared__ __align__(16) float sw2[H1C*H2C];
    __shared__ __align__(16) float sw3[H2C*CC];
    __shared__ float sp1[2*H1C];
    __shared__ float sp2[2*H2C];
    __shared__ __align__(16) float h2sT[H2C*128];
    __shared__ float ss[CC], sq[CC];
    int t = threadIdx.x;
    if(t < 7*H1C) sw1[t]=w1[t];
    if(t < 2*H1C) sp1[t]=g_par1[t];
    if(t < 2*H2C) sp2[t]=g_par2[t];
    if(t < CC){ ss[t]=0.f; sq[t]=0.f; }
    for(int i=t;i<H1C*H2C;i+=128) sw2[i]=w2[i];
    for(int i=t;i<H2C*CC;i+=128) sw3[i]=w3[i];
    __syncthreads();

    int pl = t>>4;          // local point 0..7
    int c0 = (t&15)*4;      // channel group (stage B)

    float sreg[4], qreg[4];
    #pragma unroll
    for(int i=0;i<4;i++){ sreg[i]=0.f; qreg[i]=0.f; }

    int tile = blockIdx.x;
    float4 A = g_xc4[(tile*128 + t)*2];
    float4 B = g_xc4[(tile*128 + t)*2 + 1];

    #pragma unroll 1
    for(int it=0; it<P3T; it++){
        // ---- stage A: one thread per (point, neighbor) row; write transposed
        float x[7] = {A.x,A.y,A.z,A.w,B.x,B.y,B.z};
        float a1[H1C]; lin1(x, sw1, a1);
        float h1[H1C];
        #pragma unroll
        for(int j=0;j<H1C;j++) h1[j] = gelu(a1[j]*sp1[j] + sp1[H1C+j]);
        float a2[H2C]; lin2(h1, sw2, a2);
        #pragma unroll
        for(int j=0;j<H2C;j++) h2sT[j*128 + t] = gelu(a2[j]*sp2[j] + sp2[H2C+j]);

        // prefetch next tile's x (hidden behind stage B)
        int tilen = tile + P3G;
        if(it < P3T-1){
            A = g_xc4[(tilen*128 + t)*2];
            B = g_xc4[(tilen*128 + t)*2 + 1];
        }
        __syncthreads();

        // ---- stage B: thread = (point pl, channels c0..c0+3); q outer, k inner
        float m0=-3.4e38f, m1=-3.4e38f, m2=-3.4e38f, m3=-3.4e38f;
        const float* hbase = h2sT + pl*KN;
        #pragma unroll
        for(int kc=0;kc<2;kc++){
            u64 acc[4][4];     // [k-pair][channel]
            #pragma unroll
            for(int a=0;a<4;a++)
                #pragma unroll
                for(int b=0;b<4;b++) acc[a][b]=0ull;
            #pragma unroll 4
            for(int q=0;q<H2C;q++){
                const float* hq = hbase + q*128 + kc*8;
                ulonglong2 hA = *reinterpret_cast<const ulonglong2*>(hq);
                ulonglong2 hB = *reinterpret_cast<const ulonglong2*>(hq+4);
                float4 wv = *reinterpret_cast<const float4*>(sw3 + q*CC + c0);
                u64 w0=pk2(wv.x,wv.x), w1p=pk2(wv.y,wv.y), w2p=pk2(wv.z,wv.z), w3p=pk2(wv.w,wv.w);
                acc[0][0]=f2fma(hA.x,w0,acc[0][0]); acc[0][1]=f2fma(hA.x,w1p,acc[0][1]);
                acc[0][2]=f2fma(hA.x,w2p,acc[0][2]); acc[0][3]=f2fma(hA.x,w3p,acc[0][3]);
                acc[1][0]=f2fma(hA.y,w0,acc[1][0]); acc[1][1]=f2fma(hA.y,w1p,acc[1][1]);
                acc[1][2]=f2fma(hA.y,w2p,acc[1][2]); acc[1][3]=f2fma(hA.y,w3p,acc[1][3]);
                acc[2][0]=f2fma(hB.x,w0,acc[2][0]); acc[2][1]=f2fma(hB.x,w1p,acc[2][1]);
                acc[2][2]=f2fma(hB.x,w2p,acc[2][2]); acc[2][3]=f2fma(hB.x,w3p,acc[2][3]);
                acc[3][0]=f2fma(hB.y,w0,acc[3][0]); acc[3][1]=f2fma(hB.y,w1p,acc[3][1]);
                acc[3][2]=f2fma(hB.y,w2p,acc[3][2]); acc[3][3]=f2fma(hB.y,w3p,acc[3][3]);
            }
            #pragma unroll
            for(int kp=0;kp<4;kp++){
                float l0,h0,l1,h1v,l2,h2v,l3,h3v;
                up2(acc[kp][0],l0,h0); up2(acc[kp][1],l1,h1v);
                up2(acc[kp][2],l2,h2v); up2(acc[kp][3],l3,h3v);
                m0=fmaxf(m0,fmaxf(l0,h0)); m1=fmaxf(m1,fmaxf(l1,h1v));
                m2=fmaxf(m2,fmaxf(l2,h2v)); m3=fmaxf(m3,fmaxf(l3,h3v));
            }
        }
        int np = tile*8 + pl;
        float4 o; o.x=m0; o.y=m1; o.z=m2; o.w=m3;
        *reinterpret_cast<float4*>(g_pooled + np*CC + c0) = o;
        sreg[0]+=m0; qreg[0]+=m0*m0;
        sreg[1]+=m1; qreg[1]+=m1*m1;
        sreg[2]+=m2; qreg[2]+=m2*m2;
        sreg[3]+=m3; qreg[3]+=m3*m3;

        tile = tilen;
        __syncthreads();   // h2sT reuse
    }

    #pragma unroll
    for(int i=0;i<4;i++){
        atomicAdd(&ss[c0+i], sreg[i]);
        atomicAdd(&sq[c0+i], qreg[i]);
    }
    __syncthreads();
    if(t < CC)        atomicAdd(&g_S3[t], (double)ss[t]);
    else if(t < 2*CC) atomicAdd(&g_Q3[t-CC], (double)sq[t-CC]);
}

// fused: compose bn_nbr+bn_post, build Weff and bias — one launch
__global__ void k_tail(const float* __restrict__ gn, const float* __restrict__ gp,
                       const float* __restrict__ bp, const float* __restrict__ wp){
    __shared__ float ssc[CC], ssh[CC];
    int t = threadIdx.x;
    if(t < CC){
        double m = g_S3[t]/(double)NP;
        double v = g_Q3[t]/(double)NP - m*m;
        double rs = rsqrt(v + BNEPS);
        double gnd = (double)gn[t];
        double vy = gnd*gnd*v*rs*rs;
        double rs2 = rsqrt(vy + BNEPS);
        double sc = gnd*rs*rs2*(double)gp[t];
        ssc[t]=(float)sc;
        ssh[t]=(float)((double)bp[t] - m*sc);
    }
    __syncthreads();
    for(int i=t;i<CC*HD;i+=256) g_Weff[i] = ssc[i>>8]*wp[i];
    float b=0.f;
    for(int c=0;c<CC;c++) b += ssh[c]*wp[c*HD+t];
    g_bias[t]=b;
}

// out[n][h] = pooled[n] . Weff[:,h] + bias[h]   (200000 x 64 x 256)
// 64-point x 128-hd tiles; point pairs packed directly into f32x2 lanes.
__global__ void __launch_bounds__(256) k_pass4(float* __restrict__ out){
    __shared__ __align__(16) float sW[CC*128];
    __shared__ __align__(16) float sPT[CC*68];
    __shared__ float sB[128];
    int t=threadIdx.x;
    int n0 = blockIdx.x*64;
    int hb = blockIdx.y*128;
    for(int i=t;i<CC*128;i+=256){ int c=i>>7, hh=i&127; sW[i]=g_Weff[c*HD+hb+hh]; }
    for(int i=t;i<64*CC;i+=256){ int c=i&63, pt=i>>6; sPT[c*68+pt]=g_pooled[(n0+pt)*CC + c]; }
    if(t<128) sB[t]=g_bias[hb+t];
    __syncthreads();
    int pi=t>>5, hj=t&31;
    u64 acc[4][4];     // [point-pair][hd]
    #pragma unroll
    for(int a=0;a<4;a++)
        #pragma unroll
        for(int b=0;b<4;b++) acc[a][b]=0ull;
    const float* pb = sPT + pi*8;
    #pragma unroll 4
    for(int c=0;c<CC;c++){
        ulonglong2 pA = *reinterpret_cast<const ulonglong2*>(pb + c*68);
        ulonglong2 pB = *reinterpret_cast<const ulonglong2*>(pb + c*68 + 4);
        float4 wv = *reinterpret_cast<const float4*>(sW + c*128 + hj*4);
        u64 w0=pk2(wv.x,wv.x), w1p=pk2(wv.y,wv.y), w2p=pk2(wv.z,wv.z), w3p=pk2(wv.w,wv.w);
        acc[0][0]=f2fma(pA.x,w0,acc[0][0]); acc[0][1]=f2fma(pA.x,w1p,acc[0][1]);
        acc[0][2]=f2fma(pA.x,w2p,acc[0][2]); acc[0][3]=f2fma(pA.x,w3p,acc[0][3]);
        acc[1][0]=f2fma(pA.y,w0,acc[1][0]); acc[1][1]=f2fma(pA.y,w1p,acc[1][1]);
        acc[1][2]=f2fma(pA.y,w2p,acc[1][2]); acc[1][3]=f2fma(pA.y,w3p,acc[1][3]);
        acc[2][0]=f2fma(pB.x,w0,acc[2][0]); acc[2][1]=f2fma(pB.x,w1p,acc[2][1]);
        acc[2][2]=f2fma(pB.x,w2p,acc[2][2]); acc[2][3]=f2fma(pB.x,w3p,acc[2][3]);
        acc[3][0]=f2fma(pB.y,w0,acc[3][0]); acc[3][1]=f2fma(pB.y,w1p,acc[3][1]);
        acc[3][2]=f2fma(pB.y,w2p,acc[3][2]); acc[3][3]=f2fma(pB.y,w3p,acc[3][3]);
    }
    float b0=sB[hj*4], b1=sB[hj*4+1], b2=sB[hj*4+2], b3=sB[hj*4+3];
    #pragma unroll
    for(int pq=0;pq<4;pq++){
        float e0,o0,e1,o1,e2,o2,e3,o3;
        up2(acc[pq][0],e0,o0); up2(acc[pq][1],e1,o1);
        up2(acc[pq][2],e2,o2); up2(acc[pq][3],e3,o3);
        int np = n0 + pi*8 + pq*2;
        float4 oe; oe.x=e0+b0; oe.y=e1+b1; oe.z=e2+b2; oe.w=e3+b3;
        float4 oo; oo.x=o0+b0; oo.y=o1+b1; oo.z=o2+b2; oo.w=o3+b3;
        *reinterpret_cast<float4*>(out + np*HD + hb + hj*4) = oe;
        *reinterpret_cast<float4*>(out + (np+1)*HD + hb + hj*4) = oo;
    }
}

extern "C" void kernel_launch(void* const* d_in, const int* in_sizes, int n_in,
                              void* d_out, int out_size){
    const float* p  = (const float*)d_in[0];
    const float* f  = (const float*)d_in[1];
    const int*   gi = (const int*)  d_in[2];
    const float* w1 = (const float*)d_in[3];
    const float* g1 = (const float*)d_in[4];
    const float* b1 = (const float*)d_in[5];
    const float* w2 = (const float*)d_in[6];
    const float* g2 = (const float*)d_in[7];
    const float* b2 = (const float*)d_in[8];
    const float* w3 = (const float*)d_in[9];
    const float* gn = (const float*)d_in[10];
    const float* bn = (const float*)d_in[11];
    const float* gp = (const float*)d_in[12];
    const float* bp = (const float*)d_in[13];
    const float* wp = (const float*)d_in[14];
    float* out = (float*)d_out;
    (void)in_sizes; (void)n_in; (void)out_size; (void)bn;

    k_init   <<<1, 256>>>();
    k_pass1m <<<1250, 256>>>(p, f, gi);
    k_stats1 <<<1, H1C>>>(w1, g1, b1);
    k_pass2m <<<1250, 128>>>(w1);
    k_stats2 <<<1, H2C>>>(w2, g2, b2);
    k_pass3  <<<P3G, 128>>>(w1, w2, w3);
    k_tail   <<<1, 256>>>(gn, gp, bp, wp);
    k_pass4  <<<dim3(NP/64, 2), 256>>>(out);
}

// round 12
// speedup vs baseline: 1.9701x; 1.0656x over previous
#include <cuda_runtime.h>

#define NP 200000
#define KN 16
#define MR 3200000
#define H1C 16
#define H2C 32
#define CC 64
#define HD 256
#define BNEPS 1e-5

// ---------------- scratch (no allocations allowed) ----------------
__device__ double g_MX[7],  g_MXX[28];    // sum x, sum x x^T (triangle)
__device__ double g_MH[16], g_MHH[136];   // sum h1, sum h1 h1^T (triangle)
__device__ double g_S3[CC], g_Q3[CC];
__device__ float  g_par1[2*H1C];
__device__ float  g_par2[2*H2C];
__device__ float4 g_xc4[2*MR];            // cached gathered rows (8 floats/row), 102.4MB
__device__ float  g_pooled[NP*CC];        // 51.2MB
__device__ float  g_Weff[CC*HD];
__device__ float  g_bias[HD];

typedef unsigned long long u64;

// ---------------- packed f32x2 helpers ----------------
__device__ __forceinline__ u64 pk2(float lo, float hi){
    u64 r; asm("mov.b64 %0, {%1, %2};" : "=l"(r) : "f"(lo), "f"(hi)); return r;
}
__device__ __forceinline__ void up2(u64 v, float &lo, float &hi){
    asm("mov.b64 {%0, %1}, %2;" : "=f"(lo), "=f"(hi) : "l"(v));
}
__device__ __forceinline__ u64 f2fma(u64 a, u64 b, u64 c){
    u64 r; asm("fma.rn.f32x2 %0, %1, %2, %3;" : "=l"(r) : "l"(a), "l"(b), "l"(c)); return r;
}

__device__ __forceinline__ float gelu(float v){
    return 0.5f*v*(1.0f + erff(v*0.70710678118654752f));
}

// a = x @ w1   (w1 shared, row-major [7][16])
__device__ __forceinline__ void lin1(const float x[7], const float* sw1, float a[H1C]){
    u64 acc[8];
    #pragma unroll
    for(int u=0;u<8;u++) acc[u]=0ull;
    #pragma unroll
    for(int i=0;i<7;i++){
        u64 xp = pk2(x[i], x[i]);
        const u64* w = reinterpret_cast<const u64*>(sw1 + i*H1C);
        #pragma unroll
        for(int u=0;u<8;u++) acc[u] = f2fma(xp, w[u], acc[u]);
    }
    #pragma unroll
    for(int u=0;u<8;u++) up2(acc[u], a[2*u], a[2*u+1]);
}

// a = h @ w2   (w2 shared, row-major [16][32])
__device__ __forceinline__ void lin2(const float h[H1C], const float* sw2, float a[H2C]){
    u64 acc[16];
    #pragma unroll
    for(int u=0;u<16;u++) acc[u]=0ull;
    #pragma unroll
    for(int i=0;i<H1C;i++){
        u64 hp = pk2(h[i], h[i]);
        const u64* w = reinterpret_cast<const u64*>(sw2 + i*H2C);
        #pragma unroll
        for(int u=0;u<16;u++) acc[u] = f2fma(hp, w[u], acc[u]);
    }
    #pragma unroll
    for(int u=0;u<16;u++) up2(acc[u], a[2*u], a[2*u+1]);
}

__device__ __forceinline__ float wred(float v){
    #pragma unroll
    for(int o=16;o>0;o>>=1) v += __shfl_down_sync(0xffffffffu, v, o);
    return v;
}

__device__ __forceinline__ int tri7(int i, int k){
    if(i>k){int s=i;i=k;k=s;}
    return i*7 - (i*(i-1))/2 + (k-i);
}
__device__ __forceinline__ int tri16(int i, int k){
    if(i>k){int s=i;i=k;k=s;}
    return i*16 - (i*(i-1))/2 + (k-i);
}

// ---------------- kernels ----------------
__global__ void k_init(){
    int t = threadIdx.x;
    if(t<7)   g_MX[t]=0.0;
    if(t<28)  g_MXX[t]=0.0;
    if(t<16)  g_MH[t]=0.0;
    if(t<136) g_MHH[t]=0.0;
    if(t<CC){ g_S3[t]=0.0; g_Q3[t]=0.0; }
}

// ---- pass1 v2: thread = one point. Center loaded once, 16 neighbors gathered in
// two 8-wide independent groups (MLP~32/thread), 512B contiguous store per thread.
__device__ __forceinline__ void p1_group8(const float* __restrict__ p,
    const float* __restrict__ f, int4 ga, int4 gb,
    float px, float py, float pz, int rbase, float* sx, float* sxx){
    int idx0=ga.x, idx1=ga.y, idx2=ga.z, idx3=ga.w;
    int idx4=gb.x, idx5=gb.y, idx6=gb.z, idx7=gb.w;
    float xb[8][7];
    int ids[1];
    (void)ids;
    #define GATH(j, id) { \
        xb[j][0]=p[3*(id)]-px; xb[j][1]=p[3*(id)+1]-py; xb[j][2]=p[3*(id)+2]-pz; \
        float4 fv = *reinterpret_cast<const float4*>(f + 4*(id)); \
        xb[j][3]=fv.x; xb[j][4]=fv.y; xb[j][5]=fv.z; xb[j][6]=fv.w; }
    GATH(0,idx0) GATH(1,idx1) GATH(2,idx2) GATH(3,idx3)
    GATH(4,idx4) GATH(5,idx5) GATH(6,idx6) GATH(7,idx7)
    #undef GATH
    #pragma unroll
    for(int j=0;j<8;j++){
        int c=0;
        #pragma unroll
        for(int i=0;i<7;i++){
            sx[i] += xb[j][i];
            #pragma unroll
            for(int k=i;k<7;k++) sxx[c++] += xb[j][i]*xb[j][k];
        }
        int r = rbase + j;
        float4 A; A.x=xb[j][0]; A.y=xb[j][1]; A.z=xb[j][2]; A.w=xb[j][3];
        float4 B; B.x=xb[j][4]; B.y=xb[j][5]; B.z=xb[j][6]; B.w=0.f;
        g_xc4[2*r]   = A;
        g_xc4[2*r+1] = B;
    }
}

__global__ void __launch_bounds__(256) k_pass1m(const float* __restrict__ p,
    const float* __restrict__ f, const int* __restrict__ gi){
    int n = blockIdx.x*blockDim.x + threadIdx.x;
    float sx[7], sxx[28];
    #pragma unroll
    for(int i=0;i<7;i++) sx[i]=0.f;
    #pragma unroll
    for(int i=0;i<28;i++) sxx[i]=0.f;

    if(n < NP){
        float px = p[3*n], py = p[3*n+1], pz = p[3*n+2];
        const int4* g4 = reinterpret_cast<const int4*>(gi + n*16);
        int4 ga = g4[0], gb = g4[1];
        p1_group8(p, f, ga, gb, px, py, pz, n*16,     sx, sxx);
        int4 gc = g4[2], gd = g4[3];
        p1_group8(p, f, gc, gd, px, py, pz, n*16 + 8, sx, sxx);
    }

    __shared__ float rs[7], rm[28];
    int tt = threadIdx.x;
    if(tt<7) rs[tt]=0.f;
    if(tt<28) rm[tt]=0.f;
    __syncthreads();
    int lane = tt & 31;
    #pragma unroll
    for(int i=0;i<7;i++){ float v=wred(sx[i]); if(lane==0) atomicAdd(&rs[i],v); }
    #pragma unroll
    for(int i=0;i<28;i++){ float v=wred(sxx[i]); if(lane==0) atomicAdd(&rm[i],v); }
    __syncthreads();
    if(tt<7)  atomicAdd(&g_MX[tt],  (double)rs[tt]);
    if(tt<28) atomicAdd(&g_MXX[tt], (double)rm[tt]);
}

__global__ void k_stats1(const float* __restrict__ w1, const float* __restrict__ g1,
                         const float* __restrict__ b1){
    int j = threadIdx.x;
    if(j >= H1C) return;
    double inv = 1.0/(double)MR;
    double m = 0.0, es = 0.0;
    for(int i=0;i<7;i++){
        double wij = (double)w1[i*H1C+j];
        m += g_MX[i]*inv*wij;
        for(int k=0;k<7;k++)
            es += g_MXX[tri7(i,k)]*inv * wij * (double)w1[k*H1C+j];
    }
    double v = es - m*m;
    double rs = rsqrt(v + BNEPS);
    float sc = (float)((double)g1[j] * rs);
    g_par1[j] = sc;
    g_par1[H1C+j] = b1[j] - (float)m * sc;
}

// ---- pass2 (round-3 proven form): stream xc, h1 = gelu(bn1(x@w1)),
// lane-pair split triangle moments. 625 blocks x 256, 20 rows/thread exact.
__global__ void __launch_bounds__(256) k_pass2m(const float* __restrict__ w1){
    const int T = 625*256;
    __shared__ __align__(16) float sw1[7*H1C];
    __shared__ float sp1[2*H1C];
    int tt = threadIdx.x;
    if(tt < 7*H1C) sw1[tt]=w1[tt];
    if(tt < 2*H1C) sp1[tt]=g_par1[tt];
    __syncthreads();
    int lane = tt & 31;
    int par  = lane & 1;

    float sh[16], mh[68];
    #pragma unroll
    for(int i=0;i<16;i++) sh[i]=0.f;
    #pragma unroll
    for(int i=0;i<68;i++) mh[i]=0.f;

    int t = blockIdx.x*blockDim.x + tt;
    int r = t;
    float4 A = g_xc4[2*r], B = g_xc4[2*r+1];
    #pragma unroll 1
    for(int it=0; it<20; it++){
        float x[7] = {A.x,A.y,A.z,A.w,B.x,B.y,B.z};
        int rn = r + T;
        if(it < 19){ A = g_xc4[2*rn]; B = g_xc4[2*rn+1]; }
        r = rn;
        float a1[H1C]; lin1(x, sw1, a1);
        float h1[H1C];
        #pragma unroll
        for(int j=0;j<H1C;j++) h1[j] = gelu(a1[j]*sp1[j] + sp1[H1C+j]);
        float hp[H1C];
        #pragma unroll
        for(int j=0;j<H1C;j++) hp[j] = __shfl_xor_sync(0xffffffffu, h1[j], 1);
        #pragma unroll
        for(int j=0;j<H1C;j++) sh[j] += h1[j];
        // lane-pair split of the 136-entry triangle (sum over both rows is
        // symmetric in (h1,hp), so both parities use the unordered pair)
        if(par==0){
            int c=0;
            #pragma unroll
            for(int i=0;i<16;i++)
                #pragma unroll
                for(int k=i;k<16;k++){
                    if(c<68) mh[c] += h1[i]*h1[k] + hp[i]*hp[k];
                    c++;
                }
        } else {
            int c=0;
            #pragma unroll
            for(int i=0;i<16;i++)
                #pragma unroll
                for(int k=i;k<16;k++){
                    if(c>=68) mh[c-68] += h1[i]*h1[k] + hp[i]*hp[k];
                    c++;
                }
        }
    }
    __shared__ float rs[16], rm[136];
    if(tt<16) rs[tt]=0.f;
    if(tt<136) rm[tt]=0.f;
    __syncthreads();
    #pragma unroll
    for(int i=0;i<16;i++){ float v=wred(sh[i]); if(lane==0) atomicAdd(&rs[i],v); }
    // same-parity tree reduce (offsets even -> stays within parity class)
    #pragma unroll
    for(int e=0;e<68;e++){
        float v = mh[e];
        v += __shfl_down_sync(0xffffffffu, v, 16);
        v += __shfl_down_sync(0xffffffffu, v, 8);
        v += __shfl_down_sync(0xffffffffu, v, 4);
        v += __shfl_down_sync(0xffffffffu, v, 2);
        mh[e] = v;
    }
    if(lane==0){
        #pragma unroll
        for(int e=0;e<68;e++) atomicAdd(&rm[e], mh[e]);
    } else if(lane==1){
        #pragma unroll
        for(int e=0;e<68;e++) atomicAdd(&rm[68+e], mh[e]);
    }
    __syncthreads();
    if(tt<16)  atomicAdd(&g_MH[tt],  (double)rs[tt]);
    if(tt<136) atomicAdd(&g_MHH[tt], (double)rm[tt]);
}

__global__ void k_stats2(const float* __restrict__ w2, const float* __restrict__ g2,
                         const float* __restrict__ b2){
    int j = threadIdx.x;
    if(j >= H2C) return;
    double inv = 1.0/(double)MR;
    double m = 0.0, es = 0.0;
    for(int i=0;i<16;i++){
        double wij = (double)w2[i*H2C+j];
        m += g_MH[i]*inv*wij;
        for(int k=0;k<16;k++)
            es += g_MHH[tri16(i,k)]*inv * wij * (double)w2[k*H2C+j];
    }
    double v = es - m*m;
    double rs = rsqrt(v + BNEPS);
    float sc = (float)((double)g2[j] * rs);
    g_par2[j] = sc;
    g_par2[H2C+j] = b2[j] - (float)m * sc;
}

// ---- pass3: stream xc -> full MLP -> a3 -> max over K -> pooled + fused stats.
// h2 stored TRANSPOSED in smem: h2sT[q][row], so stage B loads k-contiguous vectors
// and w3 is loaded once per q (not per (q,k)).
#define P3G 2500
#define P3T 10
__global__ void __launch_bounds__(128) k_pass3(const float* __restrict__ w1,
    const float* __restrict__ w2, const float* __restrict__ w3){
    __shared__ __align__(16) float sw1[7*H1C];
    __shared__ __align__(16) float sw2[H1C*H2C];
    __shared__ __align__(16) float sw3[H2C*CC];
    __shared__ float sp1[2*H1C];
    __shared__ float sp2[2*H2C];
    __shared__ __align__(16) float h2sT[H2C*128];
    __shared__ float ss[CC], sq[CC];
    int t = threadIdx.x;
    if(t < 7*H1C) sw1[t]=w1[t];
    if(t < 2*H1C) sp1[t]=g_par1[t];
    if(t < 2*H2C) sp2[t]=g_par2[t];
    if(t < CC){ ss[t]=0.f; sq[t]=0.f; }
    for(int i=t;i<H1C*H2C;i+=128) sw2[i]=w2[i];
    for(int i=t;i<H2C*CC;i+=128) sw3[i]=w3[i];
    __syncthreads();

    int pl = t>>4;          // local point 0..7
    int c0 = (t&15)*4;      // channel group (stage B)

    float sreg[4], qreg[4];
    #pragma unroll
    for(int i=0;i<4;i++){ sreg[i]=0.f; qreg[i]=0.f; }

    int tile = blockIdx.x;
    float4 A = g_xc4[(tile*128 + t)*2];
    float4 B = g_xc4[(tile*128 + t)*2 + 1];

    #pragma unroll 1
    for(int it=0; it<P3T; it++){
        // ---- stage A: one thread per (point, neighbor) row; write transposed
        float x[7] = {A.x,A.y,A.z,A.w,B.x,B.y,B.z};
        float a1[H1C]; lin1(x, sw1, a1);
        float h1[H1C];
        #pragma unroll
        for(int j=0;j<H1C;j++) h1[j] = gelu(a1[j]*sp1[j] + sp1[H1C+j]);
        float a2[H2C]; lin2(h1, sw2, a2);
        #pragma unroll
        for(int j=0;j<H2C;j++) h2sT[j*128 + t] = gelu(a2[j]*sp2[j] + sp2[H2C+j]);

        // prefetch next tile's x (hidden behind stage B)
        int tilen = tile + P3G;
        if(it < P3T-1){
            A = g_xc4[(tilen*128 + t)*2];
            B = g_xc4[(tilen*128 + t)*2 + 1];
        }
        __syncthreads();

        // ---- stage B: thread = (point pl, channels c0..c0+3); q outer, k inner
        float m0=-3.4e38f, m1=-3.4e38f, m2=-3.4e38f, m3=-3.4e38f;
        const float* hbase = h2sT + pl*KN;
        #pragma unroll
        for(int kc=0;kc<2;kc++){
            u64 acc[4][4];     // [k-pair][channel]
            #pragma unroll
            for(int a=0;a<4;a++)
                #pragma unroll
                for(int b=0;b<4;b++) acc[a][b]=0ull;
            #pragma unroll 4
            for(int q=0;q<H2C;q++){
                const float* hq = hbase + q*128 + kc*8;
                ulonglong2 hA = *reinterpret_cast<const ulonglong2*>(hq);
                ulonglong2 hB = *reinterpret_cast<const ulonglong2*>(hq+4);
                float4 wv = *reinterpret_cast<const float4*>(sw3 + q*CC + c0);
                u64 w0=pk2(wv.x,wv.x), w1p=pk2(wv.y,wv.y), w2p=pk2(wv.z,wv.z), w3p=pk2(wv.w,wv.w);
                acc[0][0]=f2fma(hA.x,w0,acc[0][0]); acc[0][1]=f2fma(hA.x,w1p,acc[0][1]);
                acc[0][2]=f2fma(hA.x,w2p,acc[0][2]); acc[0][3]=f2fma(hA.x,w3p,acc[0][3]);
                acc[1][0]=f2fma(hA.y,w0,acc[1][0]); acc[1][1]=f2fma(hA.y,w1p,acc[1][1]);
                acc[1][2]=f2fma(hA.y,w2p,acc[1][2]); acc[1][3]=f2fma(hA.y,w3p,acc[1][3]);
                acc[2][0]=f2fma(hB.x,w0,acc[2][0]); acc[2][1]=f2fma(hB.x,w1p,acc[2][1]);
                acc[2][2]=f2fma(hB.x,w2p,acc[2][2]); acc[2][3]=f2fma(hB.x,w3p,acc[2][3]);
                acc[3][0]=f2fma(hB.y,w0,acc[3][0]); acc[3][1]=f2fma(hB.y,w1p,acc[3][1]);
                acc[3][2]=f2fma(hB.y,w2p,acc[3][2]); acc[3][3]=f2fma(hB.y,w3p,acc[3][3]);
            }
            #pragma unroll
            for(int kp=0;kp<4;kp++){
                float l0,h0,l1,h1v,l2,h2v,l3,h3v;
                up2(acc[kp][0],l0,h0); up2(acc[kp][1],l1,h1v);
                up2(acc[kp][2],l2,h2v); up2(acc[kp][3],l3,h3v);
                m0=fmaxf(m0,fmaxf(l0,h0)); m1=fmaxf(m1,fmaxf(l1,h1v));
                m2=fmaxf(m2,fmaxf(l2,h2v)); m3=fmaxf(m3,fmaxf(l3,h3v));
            }
        }
        int np = tile*8 + pl;
        float4 o; o.x=m0; o.y=m1; o.z=m2; o.w=m3;
        *reinterpret_cast<float4*>(g_pooled + np*CC + c0) = o;
        sreg[0]+=m0; qreg[0]+=m0*m0;
        sreg[1]+=m1; qreg[1]+=m1*m1;
        sreg[2]+=m2; qreg[2]+=m2*m2;
        sreg[3]+=m3; qreg[3]+=m3*m3;

        tile = tilen;
        __syncthreads();   // h2sT reuse
    }

    #pragma unroll
    for(int i=0;i<4;i++){
        atomicAdd(&ss[c0+i], sreg[i]);
        atomicAdd(&sq[c0+i], qreg[i]);
    }
    __syncthreads();
    if(t < CC)        atomicAdd(&g_S3[t], (double)ss[t]);
    else if(t < 2*CC) atomicAdd(&g_Q3[t-CC], (double)sq[t-CC]);
}

// fused: compose bn_nbr+bn_post, build Weff and bias — one launch
__global__ void k_tail(const float* __restrict__ gn, const float* __restrict__ gp,
                       const float* __restrict__ bp, const float* __restrict__ wp){
    __shared__ float ssc[CC], ssh[CC];
    int t = threadIdx.x;
    if(t < CC){
        double m = g_S3[t]/(double)NP;
        double v = g_Q3[t]/(double)NP - m*m;
        double rs = rsqrt(v + BNEPS);
        double gnd = (double)gn[t];
        double vy = gnd*gnd*v*rs*rs;
        double rs2 = rsqrt(vy + BNEPS);
        double sc = gnd*rs*rs2*(double)gp[t];
        ssc[t]=(float)sc;
        ssh[t]=(float)((double)bp[t] - m*sc);
    }
    __syncthreads();
    for(int i=t;i<CC*HD;i+=256) g_Weff[i] = ssc[i>>8]*wp[i];
    float b=0.f;
    for(int c=0;c<CC;c++) b += ssh[c]*wp[c*HD+t];
    g_bias[t]=b;
}

// out[n][h] = pooled[n] . Weff[:,h] + bias[h]   (200000 x 64 x 256)
// 64-point x 128-hd tiles; point pairs packed directly into f32x2 lanes.
__global__ void __launch_bounds__(256) k_pass4(float* __restrict__ out){
    __shared__ __align__(16) float sW[CC*128];
    __shared__ __align__(16) float sPT[CC*68];
    __shared__ float sB[128];
    int t=threadIdx.x;
    int n0 = blockIdx.x*64;
    int hb = blockIdx.y*128;
    for(int i=t;i<CC*128;i+=256){ int c=i>>7, hh=i&127; sW[i]=g_Weff[c*HD+hb+hh]; }
    for(int i=t;i<64*CC;i+=256){ int c=i&63, pt=i>>6; sPT[c*68+pt]=g_pooled[(n0+pt)*CC + c]; }
    if(t<128) sB[t]=g_bias[hb+t];
    __syncthreads();
    int pi=t>>5, hj=t&31;
    u64 acc[4][4];     // [point-pair][hd]
    #pragma unroll
    for(int a=0;a<4;a++)
        #pragma unroll
        for(int b=0;b<4;b++) acc[a][b]=0ull;
    const float* pb = sPT + pi*8;
    #pragma unroll 4
    for(int c=0;c<CC;c++){
        ulonglong2 pA = *reinterpret_cast<const ulonglong2*>(pb + c*68);
        ulonglong2 pB = *reinterpret_cast<const ulonglong2*>(pb + c*68 + 4);
        float4 wv = *reinterpret_cast<const float4*>(sW + c*128 + hj*4);
        u64 w0=pk2(wv.x,wv.x), w1p=pk2(wv.y,wv.y), w2p=pk2(wv.z,wv.z), w3p=pk2(wv.w,wv.w);
        acc[0][0]=f2fma(pA.x,w0,acc[0][0]); acc[0][1]=f2fma(pA.x,w1p,acc[0][1]);
        acc[0][2]=f2fma(pA.x,w2p,acc[0][2]); acc[0][3]=f2fma(pA.x,w3p,acc[0][3]);
        acc[1][0]=f2fma(pA.y,w0,acc[1][0]); acc[1][1]=f2fma(pA.y,w1p,acc[1][1]);
        acc[1][2]=f2fma(pA.y,w2p,acc[1][2]); acc[1][3]=f2fma(pA.y,w3p,acc[1][3]);
        acc[2][0]=f2fma(pB.x,w0,acc[2][0]); acc[2][1]=f2fma(pB.x,w1p,acc[2][1]);
        acc[2][2]=f2fma(pB.x,w2p,acc[2][2]); acc[2][3]=f2fma(pB.x,w3p,acc[2][3]);
        acc[3][0]=f2fma(pB.y,w0,acc[3][0]); acc[3][1]=f2fma(pB.y,w1p,acc[3][1]);
        acc[3][2]=f2fma(pB.y,w2p,acc[3][2]); acc[3][3]=f2fma(pB.y,w3p,acc[3][3]);
    }
    float b0=sB[hj*4], b1=sB[hj*4+1], b2=sB[hj*4+2], b3=sB[hj*4+3];
    #pragma unroll
    for(int pq=0;pq<4;pq++){
        float e0,o0,e1,o1,e2,o2,e3,o3;
        up2(acc[pq][0],e0,o0); up2(acc[pq][1],e1,o1);
        up2(acc[pq][2],e2,o2); up2(acc[pq][3],e3,o3);
        int np = n0 + pi*8 + pq*2;
        float4 oe; oe.x=e0+b0; oe.y=e1+b1; oe.z=e2+b2; oe.w=e3+b3;
        float4 oo; oo.x=o0+b0; oo.y=o1+b1; oo.z=o2+b2; oo.w=o3+b3;
        *reinterpret_cast<float4*>(out + np*HD + hb + hj*4) = oe;
        *reinterpret_cast<float4*>(out + (np+1)*HD + hb + hj*4) = oo;
    }
}

extern "C" void kernel_launch(void* const* d_in, const int* in_sizes, int n_in,
                              void* d_out, int out_size){
    const float* p  = (const float*)d_in[0];
    const float* f  = (const float*)d_in[1];
    const int*   gi = (const int*)  d_in[2];
    const float* w1 = (const float*)d_in[3];
    const float* g1 = (const float*)d_in[4];
    const float* b1 = (const float*)d_in[5];
    const float* w2 = (const float*)d_in[6];
    const float* g2 = (const float*)d_in[7];
    const float* b2 = (const float*)d_in[8];
    const float* w3 = (const float*)d_in[9];
    const float* gn = (const float*)d_in[10];
    const float* bn = (const float*)d_in[11];
    const float* gp = (const float*)d_in[12];
    const float* bp = (const float*)d_in[13];
    const float* wp = (const float*)d_in[14];
    float* out = (float*)d_out;
    (void)in_sizes; (void)n_in; (void)out_size; (void)bn;

    k_init   <<<1, 256>>>();
    k_pass1m <<<(NP+255)/256, 256>>>(p, f, gi);
    k_stats1 <<<1, H1C>>>(w1, g1, b1);
    k_pass2m <<<625, 256>>>(w1);
    k_stats2 <<<1, H2C>>>(w2, g2, b2);
    k_pass3  <<<P3G, 128>>>(w1, w2, w3);
    k_tail   <<<1, 256>>>(gn, gp, bp, wp);
    k_pass4  <<<dim3(NP/64, 2), 256>>>(out);
}

// round 13
// speedup vs baseline: 2.0339x; 1.0324x over previous
#include <cuda_runtime.h>

#define NP 200000
#define KN 16
#define MR 3200000
#define H1C 16
#define H2C 32
#define CC 64
#define HD 256
#define BNEPS 1e-5

// ---------------- scratch (no allocations allowed) ----------------
__device__ double g_MX[7],  g_MXX[28];    // sum x, sum x x^T (triangle)
__device__ double g_MH[16], g_MHH[136];   // sum h1, sum h1 h1^T (triangle)
__device__ double g_S3[CC], g_Q3[CC];
__device__ float  g_par1[2*H1C];
__device__ float  g_par2[2*H2C];
__device__ float4 g_xc4[2*MR];            // cached gathered rows (8 floats/row), 102.4MB
__device__ float  g_pooled[NP*CC];        // 51.2MB
__device__ float  g_Weff[CC*HD];
__device__ float  g_bias[HD];

typedef unsigned long long u64;

// ---------------- packed f32x2 helpers ----------------
__device__ __forceinline__ u64 pk2(float lo, float hi){
    u64 r; asm("mov.b64 %0, {%1, %2};" : "=l"(r) : "f"(lo), "f"(hi)); return r;
}
__device__ __forceinline__ u64 pkc(float c){ return pk2(c, c); }
__device__ __forceinline__ void up2(u64 v, float &lo, float &hi){
    asm("mov.b64 {%0, %1}, %2;" : "=f"(lo), "=f"(hi) : "l"(v));
}
__device__ __forceinline__ u64 f2fma(u64 a, u64 b, u64 c){
    u64 r; asm("fma.rn.f32x2 %0, %1, %2, %3;" : "=l"(r) : "l"(a), "l"(b), "l"(c)); return r;
}
__device__ __forceinline__ u64 f2mul(u64 a, u64 b){
    u64 r; asm("mul.rn.f32x2 %0, %1, %2;" : "=l"(r) : "l"(a), "l"(b)); return r;
}
__device__ __forceinline__ float ex2a(float x){ float r; asm("ex2.approx.f32 %0, %1;" : "=f"(r) : "f"(x)); return r; }
__device__ __forceinline__ float rcpa(float x){ float r; asm("rcp.approx.f32 %0, %1;" : "=f"(r) : "f"(x)); return r; }

// Packed exact-GELU on two floats (A&S 7.1.26 erf, |err| ~1e-6 abs):
//   s = v/sqrt(2); erf(|s|) = 1 - P(t)*exp(-s^2), t = 1/(1+0.3275911|s|)
//   gelu(v) = v * (0.5 + 0.5*sign(v)*(1 - P*e))
__device__ __forceinline__ u64 gelu2(u64 v){
    u64 s  = f2mul(v, pkc(0.70710678118654752f));
    u64 s2 = f2mul(s, s);
    u64 ne = f2mul(s2, pkc(-1.4426950408889634f));
    float n0, n1; up2(ne, n0, n1);
    u64 e  = pk2(ex2a(n0), ex2a(n1));
    u64 as = s & 0x7fffffff7fffffffull;
    u64 d  = f2fma(as, pkc(0.3275911f), pkc(1.0f));
    float d0, d1; up2(d, d0, d1);
    u64 t  = pk2(rcpa(d0), rcpa(d1));
    u64 P  = pkc(1.061405429f);
    P = f2fma(P, t, pkc(-1.453152027f));
    P = f2fma(P, t, pkc(1.421413741f));
    P = f2fma(P, t, pkc(-0.284496736f));
    P = f2fma(P, t, pkc(0.254829592f));
    P = f2mul(P, t);
    u64 y   = f2mul(P, e);
    u64 omy = f2fma(y, pkc(-1.0f), pkc(1.0f));       // 1 - y  (>= 0)
    u64 g   = omy ^ (v & 0x8000000080000000ull);     // sign(v)*(1-y)
    u64 h   = f2fma(g, pkc(0.5f), pkc(0.5f));
    return f2mul(v, h);
}

// acc = x @ w1 (packed output; w1 shared, row-major [7][16])
__device__ __forceinline__ void lin1p(const float x[7], const float* sw1, u64 acc[8]){
    #pragma unroll
    for(int u=0;u<8;u++) acc[u]=0ull;
    #pragma unroll
    for(int i=0;i<7;i++){
        u64 xp = pk2(x[i], x[i]);
        const u64* w = reinterpret_cast<const u64*>(sw1 + i*H1C);
        #pragma unroll
        for(int u=0;u<8;u++) acc[u] = f2fma(xp, w[u], acc[u]);
    }
}

// acc = h @ w2 (packed output; w2 shared, row-major [16][32])
__device__ __forceinline__ void lin2p(const float h[H1C], const float* sw2, u64 acc[16]){
    #pragma unroll
    for(int u=0;u<16;u++) acc[u]=0ull;
    #pragma unroll
    for(int i=0;i<H1C;i++){
        u64 hp = pk2(h[i], h[i]);
        const u64* w = reinterpret_cast<const u64*>(sw2 + i*H2C);
        #pragma unroll
        for(int u=0;u<16;u++) acc[u] = f2fma(hp, w[u], acc[u]);
    }
}

__device__ __forceinline__ float wred(float v){
    #pragma unroll
    for(int o=16;o>0;o>>=1) v += __shfl_down_sync(0xffffffffu, v, o);
    return v;
}

__device__ __forceinline__ int tri7(int i, int k){
    if(i>k){int s=i;i=k;k=s;}
    return i*7 - (i*(i-1))/2 + (k-i);
}
__device__ __forceinline__ int tri16(int i, int k){
    if(i>k){int s=i;i=k;k=s;}
    return i*16 - (i*(i-1))/2 + (k-i);
}

// ---------------- kernels ----------------
__global__ void k_init(){
    int t = threadIdx.x;
    if(t<7)   g_MX[t]=0.0;
    if(t<28)  g_MXX[t]=0.0;
    if(t<16)  g_MH[t]=0.0;
    if(t<136) g_MHH[t]=0.0;
    if(t<CC){ g_S3[t]=0.0; g_Q3[t]=0.0; }
}

// ---- pass1: thread = one point. Center loaded once, 16 neighbors in two 8-wide
// independent gather groups, 512B contiguous store per thread.
__device__ __forceinline__ void p1_group8(const float* __restrict__ p,
    const float* __restrict__ f, int4 ga, int4 gb,
    float px, float py, float pz, int rbase, float* sx, float* sxx){
    int idx0=ga.x, idx1=ga.y, idx2=ga.z, idx3=ga.w;
    int idx4=gb.x, idx5=gb.y, idx6=gb.z, idx7=gb.w;
    float xb[8][7];
    #define GATH(j, id) { \
        xb[j][0]=p[3*(id)]-px; xb[j][1]=p[3*(id)+1]-py; xb[j][2]=p[3*(id)+2]-pz; \
        float4 fv = *reinterpret_cast<const float4*>(f + 4*(id)); \
        xb[j][3]=fv.x; xb[j][4]=fv.y; xb[j][5]=fv.z; xb[j][6]=fv.w; }
    GATH(0,idx0) GATH(1,idx1) GATH(2,idx2) GATH(3,idx3)
    GATH(4,idx4) GATH(5,idx5) GATH(6,idx6) GATH(7,idx7)
    #undef GATH
    #pragma unroll
    for(int j=0;j<8;j++){
        int c=0;
        #pragma unroll
        for(int i=0;i<7;i++){
            sx[i] += xb[j][i];
            #pragma unroll
            for(int k=i;k<7;k++) sxx[c++] += xb[j][i]*xb[j][k];
        }
        int r = rbase + j;
        float4 A; A.x=xb[j][0]; A.y=xb[j][1]; A.z=xb[j][2]; A.w=xb[j][3];
        float4 B; B.x=xb[j][4]; B.y=xb[j][5]; B.z=xb[j][6]; B.w=0.f;
        g_xc4[2*r]   = A;
        g_xc4[2*r+1] = B;
    }
}

__global__ void __launch_bounds__(256) k_pass1m(const float* __restrict__ p,
    const float* __restrict__ f, const int* __restrict__ gi){
    int n = blockIdx.x*blockDim.x + threadIdx.x;
    float sx[7], sxx[28];
    #pragma unroll
    for(int i=0;i<7;i++) sx[i]=0.f;
    #pragma unroll
    for(int i=0;i<28;i++) sxx[i]=0.f;

    if(n < NP){
        float px = p[3*n], py = p[3*n+1], pz = p[3*n+2];
        const int4* g4 = reinterpret_cast<const int4*>(gi + n*16);
        int4 ga = g4[0], gb = g4[1];
        p1_group8(p, f, ga, gb, px, py, pz, n*16,     sx, sxx);
        int4 gc = g4[2], gd = g4[3];
        p1_group8(p, f, gc, gd, px, py, pz, n*16 + 8, sx, sxx);
    }

    __shared__ float rs[7], rm[28];
    int tt = threadIdx.x;
    if(tt<7) rs[tt]=0.f;
    if(tt<28) rm[tt]=0.f;
    __syncthreads();
    int lane = tt & 31;
    #pragma unroll
    for(int i=0;i<7;i++){ float v=wred(sx[i]); if(lane==0) atomicAdd(&rs[i],v); }
    #pragma unroll
    for(int i=0;i<28;i++){ float v=wred(sxx[i]); if(lane==0) atomicAdd(&rm[i],v); }
    __syncthreads();
    if(tt<7)  atomicAdd(&g_MX[tt],  (double)rs[tt]);
    if(tt<28) atomicAdd(&g_MXX[tt], (double)rm[tt]);
}

__global__ void k_stats1(const float* __restrict__ w1, const float* __restrict__ g1,
                         const float* __restrict__ b1){
    int j = threadIdx.x;
    if(j >= H1C) return;
    double inv = 1.0/(double)MR;
    double m = 0.0, es = 0.0;
    for(int i=0;i<7;i++){
        double wij = (double)w1[i*H1C+j];
        m += g_MX[i]*inv*wij;
        for(int k=0;k<7;k++)
            es += g_MXX[tri7(i,k)]*inv * wij * (double)w1[k*H1C+j];
    }
    double v = es - m*m;
    double rs = rsqrt(v + BNEPS);
    float sc = (float)((double)g1[j] * rs);
    g_par1[j] = sc;
    g_par1[H1C+j] = b1[j] - (float)m * sc;
}

// ---- pass2: stream xc, h1 = gelu2(bn1(x@w1)) fully packed, lane-pair split
// triangle moments. 625 blocks x 256, 20 rows/thread exact.
__global__ void __launch_bounds__(256) k_pass2m(const float* __restrict__ w1){
    const int T = 625*256;
    __shared__ __align__(16) float sw1[7*H1C];
    __shared__ __align__(16) float sp1[2*H1C];
    int tt = threadIdx.x;
    if(tt < 7*H1C) sw1[tt]=w1[tt];
    if(tt < 2*H1C) sp1[tt]=g_par1[tt];
    __syncthreads();
    int lane = tt & 31;
    int par  = lane & 1;
    const u64* scp = reinterpret_cast<const u64*>(sp1);
    const u64* shp = reinterpret_cast<const u64*>(sp1 + H1C);

    float sh[16], mh[68];
    #pragma unroll
    for(int i=0;i<16;i++) sh[i]=0.f;
    #pragma unroll
    for(int i=0;i<68;i++) mh[i]=0.f;

    int t = blockIdx.x*blockDim.x + tt;
    int r = t;
    float4 A = g_xc4[2*r], B = g_xc4[2*r+1];
    #pragma unroll 1
    for(int it=0; it<20; it++){
        float x[7] = {A.x,A.y,A.z,A.w,B.x,B.y,B.z};
        int rn = r + T;
        if(it < 19){ A = g_xc4[2*rn]; B = g_xc4[2*rn+1]; }
        r = rn;
        u64 acc[8]; lin1p(x, sw1, acc);
        float h1[H1C];
        #pragma unroll
        for(int u=0;u<8;u++){
            u64 hv = gelu2(f2fma(acc[u], scp[u], shp[u]));
            up2(hv, h1[2*u], h1[2*u+1]);
        }
        float hp[H1C];
        #pragma unroll
        for(int j=0;j<H1C;j++) hp[j] = __shfl_xor_sync(0xffffffffu, h1[j], 1);
        #pragma unroll
        for(int j=0;j<H1C;j++) sh[j] += h1[j];
        // lane-pair split of the 136-entry triangle (row-pair sum is symmetric)
        if(par==0){
            int c=0;
            #pragma unroll
            for(int i=0;i<16;i++)
                #pragma unroll
                for(int k=i;k<16;k++){
                    if(c<68) mh[c] += h1[i]*h1[k] + hp[i]*hp[k];
                    c++;
                }
        } else {
            int c=0;
            #pragma unroll
            for(int i=0;i<16;i++)
                #pragma unroll
                for(int k=i;k<16;k++){
                    if(c>=68) mh[c-68] += h1[i]*h1[k] + hp[i]*hp[k];
                    c++;
                }
        }
    }
    __shared__ float rs[16], rm[136];
    if(tt<16) rs[tt]=0.f;
    if(tt<136) rm[tt]=0.f;
    __syncthreads();
    #pragma unroll
    for(int i=0;i<16;i++){ float v=wred(sh[i]); if(lane==0) atomicAdd(&rs[i],v); }
    #pragma unroll
    for(int e=0;e<68;e++){
        float v = mh[e];
        v += __shfl_down_sync(0xffffffffu, v, 16);
        v += __shfl_down_sync(0xffffffffu, v, 8);
        v += __shfl_down_sync(0xffffffffu, v, 4);
        v += __shfl_down_sync(0xffffffffu, v, 2);
        mh[e] = v;
    }
    if(lane==0){
        #pragma unroll
        for(int e=0;e<68;e++) atomicAdd(&rm[e], mh[e]);
    } else if(lane==1){
        #pragma unroll
        for(int e=0;e<68;e++) atomicAdd(&rm[68+e], mh[e]);
    }
    __syncthreads();
    if(tt<16)  atomicAdd(&g_MH[tt],  (double)rs[tt]);
    if(tt<136) atomicAdd(&g_MHH[tt], (double)rm[tt]);
}

__global__ void k_stats2(const float* __restrict__ w2, const float* __restrict__ g2,
                         const float* __restrict__ b2){
    int j = threadIdx.x;
    if(j >= H2C) return;
    double inv = 1.0/(double)MR;
    double m = 0.0, es = 0.0;
    for(int i=0;i<16;i++){
        double wij = (double)w2[i*H2C+j];
        m += g_MH[i]*inv*wij;
        for(int k=0;k<16;k++)
            es += g_MHH[tri16(i,k)]*inv * wij * (double)w2[k*H2C+j];
    }
    double v = es - m*m;
    double rs = rsqrt(v + BNEPS);
    float sc = (float)((double)g2[j] * rs);
    g_par2[j] = sc;
    g_par2[H2C+j] = b2[j] - (float)m * sc;
}

// ---- pass3: stream xc -> full MLP (packed gelu) -> a3 -> max over K -> pooled
// + fused stats. h2 transposed in smem; stage B q-outer with w3 loaded once per q.
#define P3G 2500
#define P3T 10
__global__ void __launch_bounds__(128) k_pass3(const float* __restrict__ w1,
    const float* __restrict__ w2, const float* __restrict__ w3){
    __shared__ __align__(16) float sw1[7*H1C];
    __shared__ __align__(16) float sw2[H1C*H2C];
    __shared__ __align__(16) float sw3[H2C*CC];
    __shared__ __align__(16) float sp1[2*H1C];
    __shared__ __align__(16) float sp2[2*H2C];
    __shared__ __align__(16) float h2sT[H2C*128];
    __shared__ float ss[CC], sq[CC];
    int t = threadIdx.x;
    if(t < 7*H1C) sw1[t]=w1[t];
    if(t < 2*H1C) sp1[t]=g_par1[t];
    if(t < 2*H2C) sp2[t]=g_par2[t];
    if(t < CC){ ss[t]=0.f; sq[t]=0.f; }
    for(int i=t;i<H1C*H2C;i+=128) sw2[i]=w2[i];
    for(int i=t;i<H2C*CC;i+=128) sw3[i]=w3[i];
    __syncthreads();

    const u64* scp1 = reinterpret_cast<const u64*>(sp1);
    const u64* shp1 = reinterpret_cast<const u64*>(sp1 + H1C);
    const u64* scp2 = reinterpret_cast<const u64*>(sp2);
    const u64* shp2 = reinterpret_cast<const u64*>(sp2 + H2C);

    int pl = t>>4;          // local point 0..7
    int c0 = (t&15)*4;      // channel group (stage B)

    float sreg[4], qreg[4];
    #pragma unroll
    for(int i=0;i<4;i++){ sreg[i]=0.f; qreg[i]=0.f; }

    int tile = blockIdx.x;
    float4 A = g_xc4[(tile*128 + t)*2];
    float4 B = g_xc4[(tile*128 + t)*2 + 1];

    #pragma unroll 1
    for(int it=0; it<P3T; it++){
        // ---- stage A: one thread per (point, neighbor) row; write transposed
        float x[7] = {A.x,A.y,A.z,A.w,B.x,B.y,B.z};
        u64 a1p[8]; lin1p(x, sw1, a1p);
        float h1[H1C];
        #pragma unroll
        for(int u=0;u<8;u++){
            u64 hv = gelu2(f2fma(a1p[u], scp1[u], shp1[u]));
            up2(hv, h1[2*u], h1[2*u+1]);
        }
        u64 a2p[16]; lin2p(h1, sw2, a2p);
        #pragma unroll
        for(int u=0;u<16;u++){
            u64 hv = gelu2(f2fma(a2p[u], scp2[u], shp2[u]));
            float lo, hi; up2(hv, lo, hi);
            h2sT[(2*u)*128 + t]   = lo;
            h2sT[(2*u+1)*128 + t] = hi;
        }

        // prefetch next tile's x (hidden behind stage B)
        int tilen = tile + P3G;
        if(it < P3T-1){
            A = g_xc4[(tilen*128 + t)*2];
            B = g_xc4[(tilen*128 + t)*2 + 1];
        }
        __syncthreads();

        // ---- stage B: thread = (point pl, channels c0..c0+3); q outer, 16 k inner
        u64 acc[8][4];
        #pragma unroll
        for(int a=0;a<8;a++)
            #pragma unroll
            for(int b=0;b<4;b++) acc[a][b]=0ull;
        const float* hbase = h2sT + pl*KN;
        #pragma unroll 4
        for(int q=0;q<H2C;q++){
            const float* hq = hbase + q*128;
            ulonglong2 hA = *reinterpret_cast<const ulonglong2*>(hq);
            ulonglong2 hB = *reinterpret_cast<const ulonglong2*>(hq+4);
            ulonglong2 hC = *reinterpret_cast<const ulonglong2*>(hq+8);
            ulonglong2 hD = *reinterpret_cast<const ulonglong2*>(hq+12);
            float4 wv = *reinterpret_cast<const float4*>(sw3 + q*CC + c0);
            u64 wp4[4] = {pk2(wv.x,wv.x), pk2(wv.y,wv.y), pk2(wv.z,wv.z), pk2(wv.w,wv.w)};
            u64 hk[8] = {hA.x,hA.y,hB.x,hB.y,hC.x,hC.y,hD.x,hD.y};
            #pragma unroll
            for(int kp=0;kp<8;kp++)
                #pragma unroll
                for(int ch=0;ch<4;ch++)
                    acc[kp][ch]=f2fma(hk[kp], wp4[ch], acc[kp][ch]);
        }
        float m[4] = {-3.4e38f,-3.4e38f,-3.4e38f,-3.4e38f};
        #pragma unroll
        for(int kp=0;kp<8;kp++)
            #pragma unroll
            for(int ch=0;ch<4;ch++){
                float lo, hi; up2(acc[kp][ch], lo, hi);
                m[ch] = fmaxf(m[ch], fmaxf(lo, hi));
            }
        int np = tile*8 + pl;
        float4 o; o.x=m[0]; o.y=m[1]; o.z=m[2]; o.w=m[3];
        *reinterpret_cast<float4*>(g_pooled + np*CC + c0) = o;
        #pragma unroll
        for(int ch=0;ch<4;ch++){ sreg[ch]+=m[ch]; qreg[ch]+=m[ch]*m[ch]; }

        tile = tilen;
        __syncthreads();   // h2sT reuse
    }

    #pragma unroll
    for(int i=0;i<4;i++){
        atomicAdd(&ss[c0+i], sreg[i]);
        atomicAdd(&sq[c0+i], qreg[i]);
    }
    __syncthreads();
    if(t < CC)        atomicAdd(&g_S3[t], (double)ss[t]);
    else if(t < 2*CC) atomicAdd(&g_Q3[t-CC], (double)sq[t-CC]);
}

// fused: compose bn_nbr+bn_post, build Weff and bias — one launch
__global__ void k_tail(const float* __restrict__ gn, const float* __restrict__ gp,
                       const float* __restrict__ bp, const float* __restrict__ wp){
    __shared__ float ssc[CC], ssh[CC];
    int t = threadIdx.x;
    if(t < CC){
        double m = g_S3[t]/(double)NP;
        double v = g_Q3[t]/(double)NP - m*m;
        double rs = rsqrt(v + BNEPS);
        double gnd = (double)gn[t];
        double vy = gnd*gnd*v*rs*rs;
        double rs2 = rsqrt(vy + BNEPS);
        double sc = gnd*rs*rs2*(double)gp[t];
        ssc[t]=(float)sc;
        ssh[t]=(float)((double)bp[t] - m*sc);
    }
    __syncthreads();
    for(int i=t;i<CC*HD;i+=256) g_Weff[i] = ssc[i>>8]*wp[i];
    float b=0.f;
    for(int c=0;c<CC;c++) b += ssh[c]*wp[c*HD+t];
    g_bias[t]=b;
}

// out[n][h] = pooled[n] . Weff[:,h] + bias[h]   (200000 x 64 x 256)
__global__ void __launch_bounds__(256) k_pass4(float* __restrict__ out){
    __shared__ __align__(16) float sW[CC*128];
    __shared__ __align__(16) float sPT[CC*68];
    __shared__ float sB[128];
    int t=threadIdx.x;
    int n0 = blockIdx.x*64;
    int hb = blockIdx.y*128;
    for(int i=t;i<CC*128;i+=256){ int c=i>>7, hh=i&127; sW[i]=g_Weff[c*HD+hb+hh]; }
    for(int i=t;i<64*CC;i+=256){ int c=i&63, pt=i>>6; sPT[c*68+pt]=g_pooled[(n0+pt)*CC + c]; }
    if(t<128) sB[t]=g_bias[hb+t];
    __syncthreads();
    int pi=t>>5, hj=t&31;
    u64 acc[4][4];     // [point-pair][hd]
    #pragma unroll
    for(int a=0;a<4;a++)
        #pragma unroll
        for(int b=0;b<4;b++) acc[a][b]=0ull;
    const float* pb = sPT + pi*8;
    #pragma unroll 4
    for(int c=0;c<CC;c++){
        ulonglong2 pA = *reinterpret_cast<const ulonglong2*>(pb + c*68);
        ulonglong2 pB = *reinterpret_cast<const ulonglong2*>(pb + c*68 + 4);
        float4 wv = *reinterpret_cast<const float4*>(sW + c*128 + hj*4);
        u64 w0=pk2(wv.x,wv.x), w1p=pk2(wv.y,wv.y), w2p=pk2(wv.z,wv.z), w3p=pk2(wv.w,wv.w);
        acc[0][0]=f2fma(pA.x,w0,acc[0][0]); acc[0][1]=f2fma(pA.x,w1p,acc[0][1]);
        acc[0][2]=f2fma(pA.x,w2p,acc[0][2]); acc[0][3]=f2fma(pA.x,w3p,acc[0][3]);
        acc[1][0]=f2fma(pA.y,w0,acc[1][0]); acc[1][1]=f2fma(pA.y,w1p,acc[1][1]);
        acc[1][2]=f2fma(pA.y,w2p,acc[1][2]); acc[1][3]=f2fma(pA.y,w3p,acc[1][3]);
        acc[2][0]=f2fma(pB.x,w0,acc[2][0]); acc[2][1]=f2fma(pB.x,w1p,acc[2][1]);
        acc[2][2]=f2fma(pB.x,w2p,acc[2][2]); acc[2][3]=f2fma(pB.x,w3p,acc[2][3]);
        acc[3][0]=f2fma(pB.y,w0,acc[3][0]); acc[3][1]=f2fma(pB.y,w1p,acc[3][1]);
        acc[3][2]=f2fma(pB.y,w2p,acc[3][2]); acc[3][3]=f2fma(pB.y,w3p,acc[3][3]);
    }
    float b0=sB[hj*4], b1=sB[hj*4+1], b2=sB[hj*4+2], b3=sB[hj*4+3];
    #pragma unroll
    for(int pq=0;pq<4;pq++){
        float e0,o0,e1,o1,e2,o2,e3,o3;
        up2(acc[pq][0],e0,o0); up2(acc[pq][1],e1,o1);
        up2(acc[pq][2],e2,o2); up2(acc[pq][3],e3,o3);
        int np = n0 + pi*8 + pq*2;
        float4 oe; oe.x=e0+b0; oe.y=e1+b1; oe.z=e2+b2; oe.w=e3+b3;
        float4 oo; oo.x=o0+b0; oo.y=o1+b1; oo.z=o2+b2; oo.w=o3+b3;
        *reinterpret_cast<float4*>(out + np*HD + hb + hj*4) = oe;
        *reinterpret_cast<float4*>(out + (np+1)*HD + hb + hj*4) = oo;
    }
}

extern "C" void kernel_launch(void* const* d_in, const int* in_sizes, int n_in,
                              void* d_out, int out_size){
    const float* p  = (const float*)d_in[0];
    const float* f  = (const float*)d_in[1];
    const int*   gi = (const int*)  d_in[2];
    const float* w1 = (const float*)d_in[3];
    const float* g1 = (const float*)d_in[4];
    const float* b1 = (const float*)d_in[5];
    const float* w2 = (const float*)d_in[6];
    const float* g2 = (const float*)d_in[7];
    const float* b2 = (const float*)d_in[8];
    const float* w3 = (const float*)d_in[9];
    const float* gn = (const float*)d_in[10];
    const float* bn = (const float*)d_in[11];
    const float* gp = (const float*)d_in[12];
    const float* bp = (const float*)d_in[13];
    const float* wp = (const float*)d_in[14];
    float* out = (float*)d_out;
    (void)in_sizes; (void)n_in; (void)out_size; (void)bn;

    k_init   <<<1, 256>>>();
    k_pass1m <<<(NP+255)/256, 256>>>(p, f, gi);
    k_stats1 <<<1, H1C>>>(w1, g1, b1);
    k_pass2m <<<625, 256>>>(w1);
    k_stats2 <<<1, H2C>>>(w2, g2, b2);
    k_pass3  <<<P3G, 128>>>(w1, w2, w3);
    k_tail   <<<1, 256>>>(gn, gp, bp, wp);
    k_pass4  <<<dim3(NP/64, 2), 256>>>(out);
}

// round 14
// speedup vs baseline: 2.0542x; 1.0100x over previous
#include <cuda_runtime.h>

#define NP 200000
#define KN 16
#define MR 3200000
#define H1C 16
#define H2C 32
#define CC 64
#define HD 256
#define BNEPS 1e-5

// ---------------- scratch (no allocations allowed) ----------------
__device__ double g_MX[7],  g_MXX[28];    // sum x, sum x x^T (triangle)
__device__ double g_MH[16], g_MHH[136];   // sum h1, sum h1 h1^T (triangle)
__device__ double g_S3[CC], g_Q3[CC];
__device__ float  g_par1[2*H1C];
__device__ float  g_par2[2*H2C];
__device__ float4 g_xc4[2*MR];            // cached gathered rows (8 floats/row), 102.4MB
__device__ float  g_pooled[NP*CC];        // 51.2MB
__device__ float  g_Weff[CC*HD];
__device__ float  g_bias[HD];

typedef unsigned long long u64;

// ---------------- packed f32x2 helpers ----------------
__device__ __forceinline__ u64 pk2(float lo, float hi){
    u64 r; asm("mov.b64 %0, {%1, %2};" : "=l"(r) : "f"(lo), "f"(hi)); return r;
}
__device__ __forceinline__ u64 pkc(float c){ return pk2(c, c); }
__device__ __forceinline__ void up2(u64 v, float &lo, float &hi){
    asm("mov.b64 {%0, %1}, %2;" : "=f"(lo), "=f"(hi) : "l"(v));
}
__device__ __forceinline__ u64 f2fma(u64 a, u64 b, u64 c){
    u64 r; asm("fma.rn.f32x2 %0, %1, %2, %3;" : "=l"(r) : "l"(a), "l"(b), "l"(c)); return r;
}
__device__ __forceinline__ u64 f2mul(u64 a, u64 b){
    u64 r; asm("mul.rn.f32x2 %0, %1, %2;" : "=l"(r) : "l"(a), "l"(b)); return r;
}
__device__ __forceinline__ float ex2a(float x){ float r; asm("ex2.approx.f32 %0, %1;" : "=f"(r) : "f"(x)); return r; }
__device__ __forceinline__ float rcpa(float x){ float r; asm("rcp.approx.f32 %0, %1;" : "=f"(r) : "f"(x)); return r; }

// Packed exact-GELU on two floats (A&S 7.1.26 erf, |err| ~1e-6 abs):
//   s = v/sqrt(2); erf(|s|) = 1 - P(t)*exp(-s^2), t = 1/(1+0.3275911|s|)
//   gelu(v) = v * (0.5 + 0.5*sign(v)*(1 - P*e))
__device__ __forceinline__ u64 gelu2(u64 v){
    u64 s  = f2mul(v, pkc(0.70710678118654752f));
    u64 s2 = f2mul(s, s);
    u64 ne = f2mul(s2, pkc(-1.4426950408889634f));
    float n0, n1; up2(ne, n0, n1);
    u64 e  = pk2(ex2a(n0), ex2a(n1));
    u64 as = s & 0x7fffffff7fffffffull;
    u64 d  = f2fma(as, pkc(0.3275911f), pkc(1.0f));
    float d0, d1; up2(d, d0, d1);
    u64 t  = pk2(rcpa(d0), rcpa(d1));
    u64 P  = pkc(1.061405429f);
    P = f2fma(P, t, pkc(-1.453152027f));
    P = f2fma(P, t, pkc(1.421413741f));
    P = f2fma(P, t, pkc(-0.284496736f));
    P = f2fma(P, t, pkc(0.254829592f));
    P = f2mul(P, t);
    u64 y   = f2mul(P, e);
    u64 omy = f2fma(y, pkc(-1.0f), pkc(1.0f));       // 1 - y  (>= 0)
    u64 g   = omy ^ (v & 0x8000000080000000ull);     // sign(v)*(1-y)
    u64 h   = f2fma(g, pkc(0.5f), pkc(0.5f));
    return f2mul(v, h);
}

// acc = x @ w1 (packed output; w1 shared, row-major [7][16])
__device__ __forceinline__ void lin1p(const float x[7], const float* sw1, u64 acc[8]){
    #pragma unroll
    for(int u=0;u<8;u++) acc[u]=0ull;
    #pragma unroll
    for(int i=0;i<7;i++){
        u64 xp = pk2(x[i], x[i]);
        const u64* w = reinterpret_cast<const u64*>(sw1 + i*H1C);
        #pragma unroll
        for(int u=0;u<8;u++) acc[u] = f2fma(xp, w[u], acc[u]);
    }
}

// acc = h @ w2 (packed output; w2 shared, row-major [16][32])
__device__ __forceinline__ void lin2p(const float h[H1C], const float* sw2, u64 acc[16]){
    #pragma unroll
    for(int u=0;u<16;u++) acc[u]=0ull;
    #pragma unroll
    for(int i=0;i<H1C;i++){
        u64 hp = pk2(h[i], h[i]);
        const u64* w = reinterpret_cast<const u64*>(sw2 + i*H2C);
        #pragma unroll
        for(int u=0;u<16;u++) acc[u] = f2fma(hp, w[u], acc[u]);
    }
}

__device__ __forceinline__ float wred(float v){
    #pragma unroll
    for(int o=16;o>0;o>>=1) v += __shfl_down_sync(0xffffffffu, v, o);
    return v;
}

__device__ __forceinline__ int tri7(int i, int k){
    if(i>k){int s=i;i=k;k=s;}
    return i*7 - (i*(i-1))/2 + (k-i);
}
__device__ __forceinline__ int tri16(int i, int k){
    if(i>k){int s=i;i=k;k=s;}
    return i*16 - (i*(i-1))/2 + (k-i);
}

// ---------------- kernels ----------------
__global__ void k_init(){
    int t = threadIdx.x;
    if(t<7)   g_MX[t]=0.0;
    if(t<28)  g_MXX[t]=0.0;
    if(t<16)  g_MH[t]=0.0;
    if(t<136) g_MHH[t]=0.0;
    if(t<CC){ g_S3[t]=0.0; g_Q3[t]=0.0; }
}

// ---- pass1: thread = one point. Center loaded once, 16 neighbors in two 8-wide
// independent gather groups, 512B contiguous store per thread.
__device__ __forceinline__ void p1_group8(const float* __restrict__ p,
    const float* __restrict__ f, int4 ga, int4 gb,
    float px, float py, float pz, int rbase, float* sx, float* sxx){
    int idx0=ga.x, idx1=ga.y, idx2=ga.z, idx3=ga.w;
    int idx4=gb.x, idx5=gb.y, idx6=gb.z, idx7=gb.w;
    float xb[8][7];
    #define GATH(j, id) { \
        xb[j][0]=p[3*(id)]-px; xb[j][1]=p[3*(id)+1]-py; xb[j][2]=p[3*(id)+2]-pz; \
        float4 fv = *reinterpret_cast<const float4*>(f + 4*(id)); \
        xb[j][3]=fv.x; xb[j][4]=fv.y; xb[j][5]=fv.z; xb[j][6]=fv.w; }
    GATH(0,idx0) GATH(1,idx1) GATH(2,idx2) GATH(3,idx3)
    GATH(4,idx4) GATH(5,idx5) GATH(6,idx6) GATH(7,idx7)
    #undef GATH
    #pragma unroll
    for(int j=0;j<8;j++){
        int c=0;
        #pragma unroll
        for(int i=0;i<7;i++){
            sx[i] += xb[j][i];
            #pragma unroll
            for(int k=i;k<7;k++) sxx[c++] += xb[j][i]*xb[j][k];
        }
        int r = rbase + j;
        float4 A; A.x=xb[j][0]; A.y=xb[j][1]; A.z=xb[j][2]; A.w=xb[j][3];
        float4 B; B.x=xb[j][4]; B.y=xb[j][5]; B.z=xb[j][6]; B.w=0.f;
        g_xc4[2*r]   = A;
        g_xc4[2*r+1] = B;
    }
}

__global__ void __launch_bounds__(256) k_pass1m(const float* __restrict__ p,
    const float* __restrict__ f, const int* __restrict__ gi){
    int n = blockIdx.x*blockDim.x + threadIdx.x;
    float sx[7], sxx[28];
    #pragma unroll
    for(int i=0;i<7;i++) sx[i]=0.f;
    #pragma unroll
    for(int i=0;i<28;i++) sxx[i]=0.f;

    if(n < NP){
        float px = p[3*n], py = p[3*n+1], pz = p[3*n+2];
        const int4* g4 = reinterpret_cast<const int4*>(gi + n*16);
        int4 ga = g4[0], gb = g4[1];
        p1_group8(p, f, ga, gb, px, py, pz, n*16,     sx, sxx);
        int4 gc = g4[2], gd = g4[3];
        p1_group8(p, f, gc, gd, px, py, pz, n*16 + 8, sx, sxx);
    }

    __shared__ float rs[7], rm[28];
    int tt = threadIdx.x;
    if(tt<7) rs[tt]=0.f;
    if(tt<28) rm[tt]=0.f;
    __syncthreads();
    int lane = tt & 31;
    #pragma unroll
    for(int i=0;i<7;i++){ float v=wred(sx[i]); if(lane==0) atomicAdd(&rs[i],v); }
    #pragma unroll
    for(int i=0;i<28;i++){ float v=wred(sxx[i]); if(lane==0) atomicAdd(&rm[i],v); }
    __syncthreads();
    if(tt<7)  atomicAdd(&g_MX[tt],  (double)rs[tt]);
    if(tt<28) atomicAdd(&g_MXX[tt], (double)rm[tt]);
}

__global__ void k_stats1(const float* __restrict__ w1, const float* __restrict__ g1,
                         const float* __restrict__ b1){
    int j = threadIdx.x;
    if(j >= H1C) return;
    double inv = 1.0/(double)MR;
    double m = 0.0, es = 0.0;
    for(int i=0;i<7;i++){
        double wij = (double)w1[i*H1C+j];
        m += g_MX[i]*inv*wij;
        for(int k=0;k<7;k++)
            es += g_MXX[tri7(i,k)]*inv * wij * (double)w1[k*H1C+j];
    }
    double v = es - m*m;
    double rs = rsqrt(v + BNEPS);
    float sc = (float)((double)g1[j] * rs);
    g_par1[j] = sc;
    g_par1[H1C+j] = b1[j] - (float)m * sc;
}

// ---- pass2: stream xc, h1 = gelu2(bn1(x@w1)) fully packed, lane-pair split
// triangle moments. 625 blocks x 256, 20 rows/thread exact.
__global__ void __launch_bounds__(256) k_pass2m(const float* __restrict__ w1){
    const int T = 625*256;
    __shared__ __align__(16) float sw1[7*H1C];
    __shared__ __align__(16) float sp1[2*H1C];
    int tt = threadIdx.x;
    if(tt < 7*H1C) sw1[tt]=w1[tt];
    if(tt < 2*H1C) sp1[tt]=g_par1[tt];
    __syncthreads();
    int lane = tt & 31;
    int par  = lane & 1;
    const u64* scp = reinterpret_cast<const u64*>(sp1);
    const u64* shp = reinterpret_cast<const u64*>(sp1 + H1C);

    float sh[16], mh[68];
    #pragma unroll
    for(int i=0;i<16;i++) sh[i]=0.f;
    #pragma unroll
    for(int i=0;i<68;i++) mh[i]=0.f;

    int t = blockIdx.x*blockDim.x + tt;
    int r = t;
    float4 A = g_xc4[2*r], B = g_xc4[2*r+1];
    #pragma unroll 1
    for(int it=0; it<20; it++){
        float x[7] = {A.x,A.y,A.z,A.w,B.x,B.y,B.z};
        int rn = r + T;
        if(it < 19){ A = g_xc4[2*rn]; B = g_xc4[2*rn+1]; }
        r = rn;
        u64 acc[8]; lin1p(x, sw1, acc);
        float h1[H1C];
        #pragma unroll
        for(int u=0;u<8;u++){
            u64 hv = gelu2(f2fma(acc[u], scp[u], shp[u]));
            up2(hv, h1[2*u], h1[2*u+1]);
        }
        float hp[H1C];
        #pragma unroll
        for(int j=0;j<H1C;j++) hp[j] = __shfl_xor_sync(0xffffffffu, h1[j], 1);
        #pragma unroll
        for(int j=0;j<H1C;j++) sh[j] += h1[j];
        // lane-pair split of the 136-entry triangle (row-pair sum is symmetric)
        if(par==0){
            int c=0;
            #pragma unroll
            for(int i=0;i<16;i++)
                #pragma unroll
                for(int k=i;k<16;k++){
                    if(c<68) mh[c] += h1[i]*h1[k] + hp[i]*hp[k];
                    c++;
                }
        } else {
            int c=0;
            #pragma unroll
            for(int i=0;i<16;i++)
                #pragma unroll
                for(int k=i;k<16;k++){
                    if(c>=68) mh[c-68] += h1[i]*h1[k] + hp[i]*hp[k];
                    c++;
                }
        }
    }
    __shared__ float rs[16], rm[136];
    if(tt<16) rs[tt]=0.f;
    if(tt<136) rm[tt]=0.f;
    __syncthreads();
    #pragma unroll
    for(int i=0;i<16;i++){ float v=wred(sh[i]); if(lane==0) atomicAdd(&rs[i],v); }
    #pragma unroll
    for(int e=0;e<68;e++){
        float v = mh[e];
        v += __shfl_down_sync(0xffffffffu, v, 16);
        v += __shfl_down_sync(0xffffffffu, v, 8);
        v += __shfl_down_sync(0xffffffffu, v, 4);
        v += __shfl_down_sync(0xffffffffu, v, 2);
        mh[e] = v;
    }
    if(lane==0){
        #pragma unroll
        for(int e=0;e<68;e++) atomicAdd(&rm[e], mh[e]);
    } else if(lane==1){
        #pragma unroll
        for(int e=0;e<68;e++) atomicAdd(&rm[68+e], mh[e]);
    }
    __syncthreads();
    if(tt<16)  atomicAdd(&g_MH[tt],  (double)rs[tt]);
    if(tt<136) atomicAdd(&g_MHH[tt], (double)rm[tt]);
}

__global__ void k_stats2(const float* __restrict__ w2, const float* __restrict__ g2,
                         const float* __restrict__ b2){
    int j = threadIdx.x;
    if(j >= H2C) return;
    double inv = 1.0/(double)MR;
    double m = 0.0, es = 0.0;
    for(int i=0;i<16;i++){
        double wij = (double)w2[i*H2C+j];
        m += g_MH[i]*inv*wij;
        for(int k=0;k<16;k++)
            es += g_MHH[tri16(i,k)]*inv * wij * (double)w2[k*H2C+j];
    }
    double v = es - m*m;
    double rs = rsqrt(v + BNEPS);
    float sc = (float)((double)g2[j] * rs);
    g_par2[j] = sc;
    g_par2[H2C+j] = b2[j] - (float)m * sc;
}

// ---- pass3: stream xc -> full MLP (packed gelu) -> a3 -> max over K -> pooled
// + fused stats. h2 transposed in smem; stage B q-outer with w3 loaded once per q.
#define P3G 2500
#define P3T 10
__global__ void __launch_bounds__(128) k_pass3(const float* __restrict__ w1,
    const float* __restrict__ w2, const float* __restrict__ w3){
    __shared__ __align__(16) float sw1[7*H1C];
    __shared__ __align__(16) float sw2[H1C*H2C];
    __shared__ __align__(16) float sw3[H2C*CC];
    __shared__ __align__(16) float sp1[2*H1C];
    __shared__ __align__(16) float sp2[2*H2C];
    __shared__ __align__(16) float h2sT[H2C*128];
    __shared__ float ss[CC], sq[CC];
    int t = threadIdx.x;
    if(t < 7*H1C) sw1[t]=w1[t];
    if(t < 2*H1C) sp1[t]=g_par1[t];
    if(t < 2*H2C) sp2[t]=g_par2[t];
    if(t < CC){ ss[t]=0.f; sq[t]=0.f; }
    for(int i=t;i<H1C*H2C;i+=128) sw2[i]=w2[i];
    for(int i=t;i<H2C*CC;i+=128) sw3[i]=w3[i];
    __syncthreads();

    const u64* scp1 = reinterpret_cast<const u64*>(sp1);
    const u64* shp1 = reinterpret_cast<const u64*>(sp1 + H1C);
    const u64* scp2 = reinterpret_cast<const u64*>(sp2);
    const u64* shp2 = reinterpret_cast<const u64*>(sp2 + H2C);

    int pl = t>>4;          // local point 0..7
    int c0 = (t&15)*4;      // channel group (stage B)

    float sreg[4], qreg[4];
    #pragma unroll
    for(int i=0;i<4;i++){ sreg[i]=0.f; qreg[i]=0.f; }

    int tile = blockIdx.x;
    float4 A = g_xc4[(tile*128 + t)*2];
    float4 B = g_xc4[(tile*128 + t)*2 + 1];

    #pragma unroll 1
    for(int it=0; it<P3T; it++){
        // ---- stage A: one thread per (point, neighbor) row; write transposed
        float x[7] = {A.x,A.y,A.z,A.w,B.x,B.y,B.z};
        u64 a1p[8]; lin1p(x, sw1, a1p);
        float h1[H1C];
        #pragma unroll
        for(int u=0;u<8;u++){
            u64 hv = gelu2(f2fma(a1p[u], scp1[u], shp1[u]));
            up2(hv, h1[2*u], h1[2*u+1]);
        }
        u64 a2p[16]; lin2p(h1, sw2, a2p);
        #pragma unroll
        for(int u=0;u<16;u++){
            u64 hv = gelu2(f2fma(a2p[u], scp2[u], shp2[u]));
            float lo, hi; up2(hv, lo, hi);
            h2sT[(2*u)*128 + t]   = lo;
            h2sT[(2*u+1)*128 + t] = hi;
        }

        // prefetch next tile's x (hidden behind stage B)
        int tilen = tile + P3G;
        if(it < P3T-1){
            A = g_xc4[(tilen*128 + t)*2];
            B = g_xc4[(tilen*128 + t)*2 + 1];
        }
        __syncthreads();

        // ---- stage B: thread = (point pl, channels c0..c0+3); q outer, 16 k inner
        u64 acc[8][4];
        #pragma unroll
        for(int a=0;a<8;a++)
            #pragma unroll
            for(int b=0;b<4;b++) acc[a][b]=0ull;
        const float* hbase = h2sT + pl*KN;
        #pragma unroll 4
        for(int q=0;q<H2C;q++){
            const float* hq = hbase + q*128;
            ulonglong2 hA = *reinterpret_cast<const ulonglong2*>(hq);
            ulonglong2 hB = *reinterpret_cast<const ulonglong2*>(hq+4);
            ulonglong2 hC = *reinterpret_cast<const ulonglong2*>(hq+8);
            ulonglong2 hD = *reinterpret_cast<const ulonglong2*>(hq+12);
            float4 wv = *reinterpret_cast<const float4*>(sw3 + q*CC + c0);
            u64 wp4[4] = {pk2(wv.x,wv.x), pk2(wv.y,wv.y), pk2(wv.z,wv.z), pk2(wv.w,wv.w)};
            u64 hk[8] = {hA.x,hA.y,hB.x,hB.y,hC.x,hC.y,hD.x,hD.y};
            #pragma unroll
            for(int kp=0;kp<8;kp++)
                #pragma unroll
                for(int ch=0;ch<4;ch++)
                    acc[kp][ch]=f2fma(hk[kp], wp4[ch], acc[kp][ch]);
        }
        float m[4] = {-3.4e38f,-3.4e38f,-3.4e38f,-3.4e38f};
        #pragma unroll
        for(int kp=0;kp<8;kp++)
            #pragma unroll
            for(int ch=0;ch<4;ch++){
                float lo, hi; up2(acc[kp][ch], lo, hi);
                m[ch] = fmaxf(m[ch], fmaxf(lo, hi));
            }
        int np = tile*8 + pl;
        float4 o; o.x=m[0]; o.y=m[1]; o.z=m[2]; o.w=m[3];
        *reinterpret_cast<float4*>(g_pooled + np*CC + c0) = o;
        #pragma unroll
        for(int ch=0;ch<4;ch++){ sreg[ch]+=m[ch]; qreg[ch]+=m[ch]*m[ch]; }

        tile = tilen;
        __syncthreads();   // h2sT reuse
    }

    #pragma unroll
    for(int i=0;i<4;i++){
        atomicAdd(&ss[c0+i], sreg[i]);
        atomicAdd(&sq[c0+i], qreg[i]);
    }
    __syncthreads();
    if(t < CC)        atomicAdd(&g_S3[t], (double)ss[t]);
    else if(t < 2*CC) atomicAdd(&g_Q3[t-CC], (double)sq[t-CC]);
}

// fused: compose bn_nbr+bn_post, build Weff and bias — one launch
__global__ void k_tail(const float* __restrict__ gn, const float* __restrict__ gp,
                       const float* __restrict__ bp, const float* __restrict__ wp){
    __shared__ float ssc[CC], ssh[CC];
    int t = threadIdx.x;
    if(t < CC){
        double m = g_S3[t]/(double)NP;
        double v = g_Q3[t]/(double)NP - m*m;
        double rs = rsqrt(v + BNEPS);
        double gnd = (double)gn[t];
        double vy = gnd*gnd*v*rs*rs;
        double rs2 = rsqrt(vy + BNEPS);
        double sc = gnd*rs*rs2*(double)gp[t];
        ssc[t]=(float)sc;
        ssh[t]=(float)((double)bp[t] - m*sc);
    }
    __syncthreads();
    for(int i=t;i<CC*HD;i+=256) g_Weff[i] = ssc[i>>8]*wp[i];
    float b=0.f;
    for(int c=0;c<CC;c++) b += ssh[c]*wp[c*HD+t];
    g_bias[t]=b;
}

// out[n][h] = pooled[n] . Weff[:,h] + bias[h]   (200000 x 64 x 256)
__global__ void __launch_bounds__(256) k_pass4(float* __restrict__ out){
    __shared__ __align__(16) float sW[CC*128];
    __shared__ __align__(16) float sPT[CC*68];
    __shared__ float sB[128];
    int t=threadIdx.x;
    int n0 = blockIdx.x*64;
    int hb = blockIdx.y*128;
    for(int i=t;i<CC*128;i+=256){ int c=i>>7, hh=i&127; sW[i]=g_Weff[c*HD+hb+hh]; }
    for(int i=t;i<64*CC;i+=256){ int c=i&63, pt=i>>6; sPT[c*68+pt]=g_pooled[(n0+pt)*CC + c]; }
    if(t<128) sB[t]=g_bias[hb+t];
    __syncthreads();
    int pi=t>>5, hj=t&31;
    u64 acc[4][4];     // [point-pair][hd]
    #pragma unroll
    for(int a=0;a<4;a++)
        #pragma unroll
        for(int b=0;b<4;b++) acc[a][b]=0ull;
    const float* pb = sPT + pi*8;
    #pragma unroll 4
    for(int c=0;c<CC;c++){
        ulonglong2 pA = *reinterpret_cast<const ulonglong2*>(pb + c*68);
        ulonglong2 pB = *reinterpret_cast<const ulonglong2*>(pb + c*68 + 4);
        float4 wv = *reinterpret_cast<const float4*>(sW + c*128 + hj*4);
        u64 w0=pk2(wv.x,wv.x), w1p=pk2(wv.y,wv.y), w2p=pk2(wv.z,wv.z), w3p=pk2(wv.w,wv.w);
        acc[0][0]=f2fma(pA.x,w0,acc[0][0]); acc[0][1]=f2fma(pA.x,w1p,acc[0][1]);
        acc[0][2]=f2fma(pA.x,w2p,acc[0][2]); acc[0][3]=f2fma(pA.x,w3p,acc[0][3]);
        acc[1][0]=f2fma(pA.y,w0,acc[1][0]); acc[1][1]=f2fma(pA.y,w1p,acc[1][1]);
        acc[1][2]=f2fma(pA.y,w2p,acc[1][2]); acc[1][3]=f2fma(pA.y,w3p,acc[1][3]);
        acc[2][0]=f2fma(pB.x,w0,acc[2][0]); acc[2][1]=f2fma(pB.x,w1p,acc[2][1]);
        acc[2][2]=f2fma(pB.x,w2p,acc[2][2]); acc[2][3]=f2fma(pB.x,w3p,acc[2][3]);
        acc[3][0]=f2fma(pB.y,w0,acc[3][0]); acc[3][1]=f2fma(pB.y,w1p,acc[3][1]);
        acc[3][2]=f2fma(pB.y,w2p,acc[3][2]); acc[3][3]=f2fma(pB.y,w3p,acc[3][3]);
    }
    float b0=sB[hj*4], b1=sB[hj*4+1], b2=sB[hj*4+2], b3=sB[hj*4+3];
    #pragma unroll
    for(int pq=0;pq<4;pq++){
        float e0,o0,e1,o1,e2,o2,e3,o3;
        up2(acc[pq][0],e0,o0); up2(acc[pq][1],e1,o1);
        up2(acc[pq][2],e2,o2); up2(acc[pq][3],e3,o3);
        int np = n0 + pi*8 + pq*2;
        float4 oe; oe.x=e0+b0; oe.y=e1+b1; oe.z=e2+b2; oe.w=e3+b3;
        float4 oo; oo.x=o0+b0; oo.y=o1+b1; oo.z=o2+b2; oo.w=o3+b3;
        *reinterpret_cast<float4*>(out + np*HD + hb + hj*4) = oe;
        *reinterpret_cast<float4*>(out + (np+1)*HD + hb + hj*4) = oo;
    }
}

extern "C" void kernel_launch(void* const* d_in, const int* in_sizes, int n_in,
                              void* d_out, int out_size){
    const float* p  = (const float*)d_in[0];
    const float* f  = (const float*)d_in[1];
    const int*   gi = (const int*)  d_in[2];
    const float* w1 = (const float*)d_in[3];
    const float* g1 = (const float*)d_in[4];
    const float* b1 = (const float*)d_in[5];
    const float* w2 = (const float*)d_in[6];
    const float* g2 = (const float*)d_in[7];
    const float* b2 = (const float*)d_in[8];
    const float* w3 = (const float*)d_in[9];
    const float* gn = (const float*)d_in[10];
    const float* bn = (const float*)d_in[11];
    const float* gp = (const float*)d_in[12];
    const float* bp = (const float*)d_in[13];
    const float* wp = (const float*)d_in[14];
    float* out = (float*)d_out;
    (void)in_sizes; (void)n_in; (void)out_size; (void)bn;

    k_init   <<<1, 256>>>();
    k_pass1m <<<(NP+255)/256, 256>>>(p, f, gi);
    k_stats1 <<<1, H1C>>>(w1, g1, b1);
    k_pass2m <<<625, 256>>>(w1);
    k_stats2 <<<1, H2C>>>(w2, g2, b2);
    k_pass3  <<<P3G, 128>>>(w1, w2, w3);
    k_tail   <<<1, 256>>>(gn, gp, bp, wp);
    k_pass4  <<<dim3(NP/64, 2), 256>>>(out);
}